// round 7
// baseline (speedup 1.0000x reference)
#include <cuda_runtime.h>
#include <cuda_bf16.h>
#include <cstdint>

// Problem constants
constexpr int Bn = 8192;   // batch
constexpr int Dn = 1024;   // input dim (K1)
constexpr int Hn = 400;    // hidden
constexpr int Ln = 256;    // half output
constexpr int En = 16;     // experts
constexpr int K2n = 512;   // 2L (N of GEMM2)
constexpr int HP = 416;    // hidden padded to 13*32 (K of GEMM2)
constexpr int NW = 512;    // padded N rows for transposed weights

#define TILE_M 128
#define MAX_TILES 80       // >= worst case sum ceil(ci/128) = 79
#define NT1 80             // GEMM1 N-tile (5 tiles * 80 = 400 exact)

// ================= device scratch (zero-init, no allocs) =================
__device__ int   g_idx_sorted[Bn + TILE_M];
__device__ int   g_tile_expert[MAX_TILES];
__device__ int   g_tile_rowstart[MAX_TILES];
__device__ int   g_tile_rows[MAX_TILES];

// bf16 hi/lo buffers, uint4 for 16B alignment
__device__ uint4 g_x_hi[(size_t)Bn * Dn / 8];              // [Bn][1024] bf16
__device__ uint4 g_x_lo[(size_t)Bn * Dn / 8];
__device__ uint4 g_w1t_hi[(size_t)En * NW * Dn / 8];       // [E][512][1024] (n,k); rows 0..415 filled
__device__ uint4 g_w1t_lo[(size_t)En * NW * Dn / 8];
__device__ uint4 g_w2t_hi[(size_t)En * NW * HP / 8];       // [E][512][416] (n,k)
__device__ uint4 g_w2t_lo[(size_t)En * NW * HP / 8];
__device__ uint4 g_h1_hi[(size_t)(Bn + TILE_M) * HP / 8];  // [rows][416]
__device__ uint4 g_h1_lo[(size_t)(Bn + TILE_M) * HP / 8];

// ================= helpers =================
__device__ __forceinline__ uint32_t smem_u32(const void* p) {
    uint32_t a;
    asm("{ .reg .u64 t; cvta.to.shared.u64 t, %1; cvt.u32.u64 %0, t; }" : "=r"(a) : "l"(p));
    return a;
}

#define CP16(dst_u32, src_ptr) \
    asm volatile("cp.async.cg.shared.global [%0], [%1], 16;" :: "r"(dst_u32), "l"(src_ptr))
#define CP_COMMIT() asm volatile("cp.async.commit_group;" ::: "memory")
#define CP_WAIT1()  asm volatile("cp.async.wait_group 1;" ::: "memory")
#define CP_WAIT0()  asm volatile("cp.async.wait_group 0;" ::: "memory")

__device__ __forceinline__ void mma16816(float* d, const uint32_t* a, const uint32_t* b) {
    asm volatile(
        "mma.sync.aligned.m16n8k16.row.col.f32.bf16.bf16.f32 "
        "{%0,%1,%2,%3}, {%4,%5,%6,%7}, {%8,%9}, {%0,%1,%2,%3};"
        : "+f"(d[0]), "+f"(d[1]), "+f"(d[2]), "+f"(d[3])
        : "r"(a[0]), "r"(a[1]), "r"(a[2]), "r"(a[3]), "r"(b[0]), "r"(b[1]));
}

__device__ __forceinline__ void split2(float v0, float v1, uint32_t& hi, uint32_t& lo) {
    __nv_bfloat16 h0 = __float2bfloat16(v0);
    __nv_bfloat16 h1 = __float2bfloat16(v1);
    __nv_bfloat16 l0 = __float2bfloat16(v0 - __bfloat162float(h0));
    __nv_bfloat16 l1 = __float2bfloat16(v1 - __bfloat162float(h1));
    __nv_bfloat162 ph; ph.x = h0; ph.y = h1;
    __nv_bfloat162 pl; pl.x = l0; pl.y = l1;
    hi = *reinterpret_cast<uint32_t*>(&ph);
    lo = *reinterpret_cast<uint32_t*>(&pl);
}

// ================= fused sort kernel (single block) =================
// init + int64/int32 detect + count + prefix + tile list + scatter
__global__ __launch_bounds__(1024) void sort_kernel(const void* __restrict__ ai) {
    __shared__ int s_cnt[En], s_off[En], s_cur[En];
    __shared__ int s_is64;
    int t = threadIdx.x;
    if (t < En) { s_cnt[t] = 0; s_cur[t] = 0; }
    if (t == 0) s_is64 = 1;
    if (t < TILE_M) g_idx_sorted[Bn + t] = 0;
    __syncthreads();

    // detect: interpret as int64 over first Bn/2 entries (within int32 buffer too)
    const long long* a64 = (const long long*)ai;
    for (int i = t; i < Bn / 2; i += 1024) {
        long long v = a64[i];
        if (v < 0 || v >= En) s_is64 = 0;
    }
    __syncthreads();
    int is64 = s_is64;

    // count
    int vals[8];
#pragma unroll
    for (int j = 0; j < 8; j++) {
        int i = t + j * 1024;
        int v = is64 ? (int)a64[i] : ((const int*)ai)[i];
        vals[j] = v;
        atomicAdd(&s_cnt[v], 1);
    }
    __syncthreads();

    // prefix + tile list (serial, tiny)
    if (t == 0) {
        int off = 0, tb = 0;
        for (int e = 0; e < En; e++) {
            s_off[e] = off;
            int nt = (s_cnt[e] + TILE_M - 1) / TILE_M;
            for (int k = 0; k < nt; k++) {
                g_tile_expert[tb + k]   = e;
                g_tile_rowstart[tb + k] = off + k * TILE_M;
                int rem = s_cnt[e] - k * TILE_M;
                g_tile_rows[tb + k]     = rem < TILE_M ? rem : TILE_M;
            }
            tb += nt;
            off += s_cnt[e];
        }
        for (; tb < MAX_TILES; tb++) g_tile_rows[tb] = 0;
    }
    __syncthreads();

    // scatter
#pragma unroll
    for (int j = 0; j < 8; j++) {
        int i = t + j * 1024;
        int e = vals[j];
        int pos = atomicAdd(&s_cur[e], 1);
        g_idx_sorted[s_off[e] + pos] = i;
    }
}

// ================= conversions =================
// x split + h1 pad-column zeroing (cols 400..415 of every h1 row)
__global__ void split_x_kernel(const float* __restrict__ x) {
    int i = blockIdx.x * blockDim.x + threadIdx.x;
    if (i < Bn * Dn / 4) {
        float4 v = reinterpret_cast<const float4*>(x)[i];
        uint32_t h0, l0, h1, l1;
        split2(v.x, v.y, h0, l0);
        split2(v.z, v.w, h1, l1);
        uint32_t* xh = reinterpret_cast<uint32_t*>(g_x_hi);
        uint32_t* xl = reinterpret_cast<uint32_t*>(g_x_lo);
        xh[i * 2] = h0; xh[i * 2 + 1] = h1;
        xl[i * 2] = l0; xl[i * 2 + 1] = l1;
    }
    // zero h1 pad: (Bn+TILE_M) rows x 16 bf16 = 8 uint32 per row
    if (i < (Bn + TILE_M) * 8) {
        int row = i >> 3, c = i & 7;
        uint32_t* h1h = reinterpret_cast<uint32_t*>(g_h1_hi);
        uint32_t* h1l = reinterpret_cast<uint32_t*>(g_h1_lo);
        size_t o = (size_t)row * (HP / 2) + 200 + c;   // (row*416+400)/2 + c
        h1h[o] = 0;
        h1l[o] = 0;
    }
}

// W1 [E][1024(k)][400(n)] -> [E][512(n)][1024(k)] hi/lo, rows 0..415 (n>=400 zero)
__global__ void tw1_kernel(const float* __restrict__ W1) {
    __shared__ float t[32][33];
    int e = blockIdx.z, k0 = blockIdx.x * 32, n0 = blockIdx.y * 32;
    int tx = threadIdx.x, ty = threadIdx.y;   // 32 x 8
    const float* W = W1 + (size_t)e * Dn * Hn;
#pragma unroll
    for (int i = 0; i < 32; i += 8) {
        int k = k0 + ty + i, n = n0 + tx;
        t[ty + i][tx] = (n < Hn) ? W[(size_t)k * Hn + n] : 0.f;
    }
    __syncthreads();
    __nv_bfloat16* wh = reinterpret_cast<__nv_bfloat16*>(g_w1t_hi);
    __nv_bfloat16* wl = reinterpret_cast<__nv_bfloat16*>(g_w1t_lo);
#pragma unroll
    for (int i = 0; i < 32; i += 8) {
        int n = n0 + ty + i, k = k0 + tx;
        float v = t[tx][ty + i];
        __nv_bfloat16 h = __float2bfloat16(v);
        size_t o = ((size_t)e * NW + n) * Dn + k;
        wh[o] = h;
        wl[o] = __float2bfloat16(v - __bfloat162float(h));
    }
}

// W2 [E][400(k)][512(n)] -> [E][512(n)][416(k)] hi/lo, k>=400 zero
__global__ void tw2_kernel(const float* __restrict__ W2) {
    __shared__ float t[32][33];
    int e = blockIdx.z, k0 = blockIdx.x * 32, n0 = blockIdx.y * 32;
    int tx = threadIdx.x, ty = threadIdx.y;
    const float* W = W2 + (size_t)e * Hn * K2n;
#pragma unroll
    for (int i = 0; i < 32; i += 8) {
        int k = k0 + ty + i, n = n0 + tx;
        t[ty + i][tx] = (k < Hn) ? W[(size_t)k * K2n + n] : 0.f;
    }
    __syncthreads();
    __nv_bfloat16* wh = reinterpret_cast<__nv_bfloat16*>(g_w2t_hi);
    __nv_bfloat16* wl = reinterpret_cast<__nv_bfloat16*>(g_w2t_lo);
#pragma unroll
    for (int i = 0; i < 32; i += 8) {
        int n = n0 + ty + i, k = k0 + tx;
        float v = t[tx][ty + i];
        __nv_bfloat16 h = __float2bfloat16(v);
        size_t o = ((size_t)e * NW + n) * HP + k;
        wh[o] = h;
        wl[o] = __float2bfloat16(v - __bfloat162float(h));
    }
}

// ================= GEMM1: bf16 3-pass, tile 128x80 =================
// smem: [0,512) idx, [512,896) bias, [1024..) two stages
// stage rows (stride 80B, 64B data): Ahi r0-127 @0, Alo @10240,
//                                    Bhi @20480, Blo @26880
#define G1_STAGE 33280     // 416 * 80
#define G1_SMEM  (1024 + 2 * G1_STAGE)

__global__ __launch_bounds__(256) void gemm1_mma(const float* __restrict__ b1) {
    int bt = blockIdx.x;
    int rows = g_tile_rows[bt];
    if (rows == 0) return;
    int e  = g_tile_expert[bt];
    int rs = g_tile_rowstart[bt];
    int colbase = blockIdx.y * NT1;

    extern __shared__ char smem[];
    uint32_t sb = smem_u32(smem);
    int tid = threadIdx.x;
    int wid = tid >> 5, lane = tid & 31;
    int wm = wid & 3, wn = wid >> 2;      // warps: 4 (M) x 2 (N); warp tile 32x40
    int tq = lane >> 2, tr = lane & 3;

    int* idx_s = reinterpret_cast<int*>(smem);
    float* bias_s = reinterpret_cast<float*>(smem + 512);
    if (tid < TILE_M) idx_s[tid] = g_idx_sorted[rs + tid];
    if (tid < NT1) bias_s[tid] = b1[e * Hn + colbase + tid];
    __syncthreads();

    const uint4* w1h = g_w1t_hi + (size_t)e * NW * (Dn / 8);
    const uint4* w1l = g_w1t_lo + (size_t)e * NW * (Dn / 8);

    auto fill = [&](int stg, int kt) {
        uint32_t base = sb + 1024 + stg * G1_STAGE;
#pragma unroll
        for (int i = tid; i < 512; i += 256) {        // A hi/lo: 128 rows x 4 uint4
            int r = i >> 2, c4 = i & 3;
            uint32_t d = base + r * 80 + c4 * 16;
            size_t ao = (size_t)idx_s[r] * 128 + kt * 4 + c4;
            CP16(d,         g_x_hi + ao);
            CP16(d + 10240, g_x_lo + ao);
        }
#pragma unroll
        for (int i = tid; i < 320; i += 256) {        // B hi/lo: 80 rows x 4 uint4
            int r = i >> 2, c4 = i & 3;
            uint32_t d = base + 20480 + r * 80 + c4 * 16;
            size_t bo = (size_t)(colbase + r) * 128 + kt * 4 + c4;
            CP16(d,        w1h + bo);
            CP16(d + 6400, w1l + bo);
        }
    };

    float acc[2][5][4];
#pragma unroll
    for (int mt = 0; mt < 2; mt++)
#pragma unroll
        for (int nt = 0; nt < 5; nt++)
#pragma unroll
            for (int j = 0; j < 4; j++) acc[mt][nt][j] = 0.f;

    fill(0, 0); CP_COMMIT();
    for (int it = 0; it < 32; it++) {
        if (it + 1 < 32) { fill((it + 1) & 1, it + 1); CP_COMMIT(); CP_WAIT1(); }
        else CP_WAIT0();
        __syncthreads();
        const char* st = smem + 1024 + (it & 1) * G1_STAGE;
#pragma unroll
        for (int ks = 0; ks < 2; ks++) {
            int kb = ks * 32 + tr * 4;
            uint32_t ah[2][4], al[2][4], bb[5][2];
#pragma unroll
            for (int mt = 0; mt < 2; mt++) {
                int r0 = wm * 32 + mt * 16 + tq;
                ah[mt][0] = *(const uint32_t*)(st + r0 * 80 + kb);
                ah[mt][1] = *(const uint32_t*)(st + (r0 + 8) * 80 + kb);
                ah[mt][2] = *(const uint32_t*)(st + r0 * 80 + kb + 16);
                ah[mt][3] = *(const uint32_t*)(st + (r0 + 8) * 80 + kb + 16);
                al[mt][0] = *(const uint32_t*)(st + 10240 + r0 * 80 + kb);
                al[mt][1] = *(const uint32_t*)(st + 10240 + (r0 + 8) * 80 + kb);
                al[mt][2] = *(const uint32_t*)(st + 10240 + r0 * 80 + kb + 16);
                al[mt][3] = *(const uint32_t*)(st + 10240 + (r0 + 8) * 80 + kb + 16);
            }
#pragma unroll
            for (int nt = 0; nt < 5; nt++) {
                int n = wn * 40 + nt * 8 + tq;
                bb[nt][0] = *(const uint32_t*)(st + 20480 + n * 80 + kb);
                bb[nt][1] = *(const uint32_t*)(st + 20480 + n * 80 + kb + 16);
            }
#pragma unroll
            for (int mt = 0; mt < 2; mt++)
#pragma unroll
                for (int nt = 0; nt < 5; nt++) {
                    mma16816(acc[mt][nt], ah[mt], bb[nt]);   // hh
                    mma16816(acc[mt][nt], al[mt], bb[nt]);   // lh
                }
#pragma unroll
            for (int nt = 0; nt < 5; nt++) {
                int n = wn * 40 + nt * 8 + tq;
                bb[nt][0] = *(const uint32_t*)(st + 26880 + n * 80 + kb);
                bb[nt][1] = *(const uint32_t*)(st + 26880 + n * 80 + kb + 16);
            }
#pragma unroll
            for (int mt = 0; mt < 2; mt++)
#pragma unroll
                for (int nt = 0; nt < 5; nt++)
                    mma16816(acc[mt][nt], ah[mt], bb[nt]);   // hl
        }
        __syncthreads();
    }

    // epilogue: bias + relu + bf16 split -> h1 (all 80 cols real)
    uint32_t* h1h = reinterpret_cast<uint32_t*>(g_h1_hi);
    uint32_t* h1l = reinterpret_cast<uint32_t*>(g_h1_lo);
#pragma unroll
    for (int mt = 0; mt < 2; mt++) {
        int r0 = wm * 32 + mt * 16 + tq;
#pragma unroll
        for (int nt = 0; nt < 5; nt++) {
            int c = wn * 40 + nt * 8 + tr * 2;
            int gcol = colbase + c;
#pragma unroll
            for (int half = 0; half < 2; half++) {
                int r = r0 + half * 8;
                if (r >= rows) continue;
                float v0 = fmaxf(acc[mt][nt][half * 2]     + bias_s[c], 0.f);
                float v1 = fmaxf(acc[mt][nt][half * 2 + 1] + bias_s[c + 1], 0.f);
                uint32_t hi, lo;
                split2(v0, v1, hi, lo);
                size_t o = ((size_t)(rs + r) * HP + gcol) >> 1;
                h1h[o] = hi;
                h1l[o] = lo;
            }
        }
    }
}

// ================= GEMM2: bf16 3-pass, tile 128x128, K=416 =================
#define STAGE_SZ 40960
#define SMEM_SZ  (1024 + 2 * STAGE_SZ)

__global__ __launch_bounds__(256) void gemm2_mma(const float* __restrict__ b2,
                                                 float* __restrict__ out) {
    int bt = blockIdx.x;
    int rows = g_tile_rows[bt];
    if (rows == 0) return;
    int e  = g_tile_expert[bt];
    int rs = g_tile_rowstart[bt];
    int colbase = blockIdx.y * 128;

    extern __shared__ char smem[];
    uint32_t sb = smem_u32(smem);
    int tid = threadIdx.x;
    int wid = tid >> 5, lane = tid & 31;
    int wm = wid & 3, wn = wid >> 2;
    int tq = lane >> 2, tr = lane & 3;

    int* idx_s = reinterpret_cast<int*>(smem);
    float* bias_s = reinterpret_cast<float*>(smem + 512);
    if (tid < TILE_M) idx_s[tid] = g_idx_sorted[rs + tid];
    if (tid < 128) bias_s[tid] = b2[e * K2n + colbase + tid];
    __syncthreads();

    const uint4* w2h = g_w2t_hi + (size_t)e * NW * (HP / 8);
    const uint4* w2l = g_w2t_lo + (size_t)e * NW * (HP / 8);

    auto fill = [&](int stg, int kt) {
        uint32_t base = sb + 1024 + stg * STAGE_SZ;
#pragma unroll
        for (int i = tid; i < 512; i += 256) {
            int r = i >> 2, c4 = i & 3;
            uint32_t dA = base + r * 80 + c4 * 16;
            size_t ao = (size_t)(rs + r) * (HP / 8) + kt * 4 + c4;
            CP16(dA,         g_h1_hi + ao);
            CP16(dA + 10240, g_h1_lo + ao);
            uint32_t dB = base + 20480 + r * 80 + c4 * 16;
            size_t bo = (size_t)(colbase + r) * (HP / 8) + kt * 4 + c4;
            CP16(dB,         w2h + bo);
            CP16(dB + 10240, w2l + bo);
        }
    };

    float acc[2][8][4];
#pragma unroll
    for (int mt = 0; mt < 2; mt++)
#pragma unroll
        for (int nt = 0; nt < 8; nt++)
#pragma unroll
            for (int j = 0; j < 4; j++) acc[mt][nt][j] = 0.f;

    fill(0, 0); CP_COMMIT();
    for (int it = 0; it < 13; it++) {
        if (it + 1 < 13) { fill((it + 1) & 1, it + 1); CP_COMMIT(); CP_WAIT1(); }
        else CP_WAIT0();
        __syncthreads();
        const char* st = smem + 1024 + (it & 1) * STAGE_SZ;
#pragma unroll
        for (int ks = 0; ks < 2; ks++) {
            const char* As = st;
            const char* Bs = st + 20480;
            int kb = ks * 32 + tr * 4;
            uint32_t ah[2][4], al[2][4], bb[8][2];
#pragma unroll
            for (int mt = 0; mt < 2; mt++) {
                int r0 = wm * 32 + mt * 16 + tq;
                ah[mt][0] = *(const uint32_t*)(As + r0 * 80 + kb);
                ah[mt][1] = *(const uint32_t*)(As + (r0 + 8) * 80 + kb);
                ah[mt][2] = *(const uint32_t*)(As + r0 * 80 + kb + 16);
                ah[mt][3] = *(const uint32_t*)(As + (r0 + 8) * 80 + kb + 16);
                al[mt][0] = *(const uint32_t*)(As + 10240 + r0 * 80 + kb);
                al[mt][1] = *(const uint32_t*)(As + 10240 + (r0 + 8) * 80 + kb);
                al[mt][2] = *(const uint32_t*)(As + 10240 + r0 * 80 + kb + 16);
                al[mt][3] = *(const uint32_t*)(As + 10240 + (r0 + 8) * 80 + kb + 16);
            }
#pragma unroll
            for (int nt = 0; nt < 8; nt++) {
                int n = wn * 64 + nt * 8 + tq;
                bb[nt][0] = *(const uint32_t*)(Bs + n * 80 + kb);
                bb[nt][1] = *(const uint32_t*)(Bs + n * 80 + kb + 16);
            }
#pragma unroll
            for (int mt = 0; mt < 2; mt++)
#pragma unroll
                for (int nt = 0; nt < 8; nt++) {
                    mma16816(acc[mt][nt], ah[mt], bb[nt]);
                    mma16816(acc[mt][nt], al[mt], bb[nt]);
                }
#pragma unroll
            for (int nt = 0; nt < 8; nt++) {
                int n = wn * 64 + nt * 8 + tq;
                bb[nt][0] = *(const uint32_t*)(Bs + 10240 + n * 80 + kb);
                bb[nt][1] = *(const uint32_t*)(Bs + 10240 + n * 80 + kb + 16);
            }
#pragma unroll
            for (int mt = 0; mt < 2; mt++)
#pragma unroll
                for (int nt = 0; nt < 8; nt++)
                    mma16816(acc[mt][nt], ah[mt], bb[nt]);
        }
        __syncthreads();
    }

#pragma unroll
    for (int mt = 0; mt < 2; mt++) {
        int r0 = wm * 32 + mt * 16 + tq;
#pragma unroll
        for (int nt = 0; nt < 8; nt++) {
            int c = wn * 64 + nt * 8 + tr * 2;
            int gcol = colbase + c;
#pragma unroll
            for (int half = 0; half < 2; half++) {
                int r = r0 + half * 8;
                if (r >= rows) continue;
                int b = idx_s[r];
                float2 v;
                v.x = acc[mt][nt][half * 2]     + bias_s[c];
                v.y = acc[mt][nt][half * 2 + 1] + bias_s[c + 1];
                float* dst = (gcol < Ln)
                    ? out + (size_t)b * Ln + gcol
                    : out + (size_t)Bn * Ln + (size_t)b * Ln + (gcol - Ln);
                *reinterpret_cast<float2*>(dst) = v;
            }
        }
    }
}

// ================= launch =================
extern "C" void kernel_launch(void* const* d_in, const int* in_sizes, int n_in,
                              void* d_out, int out_size) {
    const float* x  = (const float*)d_in[0];
    const void*  ai = d_in[1];
    const float* W1 = (const float*)d_in[2];
    const float* b1 = (const float*)d_in[3];
    const float* W2 = (const float*)d_in[4];
    const float* b2 = (const float*)d_in[5];
    float* out = (float*)d_out;

    cudaFuncSetAttribute(gemm1_mma, cudaFuncAttributeMaxDynamicSharedMemorySize, G1_SMEM);
    cudaFuncSetAttribute(gemm2_mma, cudaFuncAttributeMaxDynamicSharedMemorySize, SMEM_SZ);

    sort_kernel<<<1, 1024>>>(ai);
    split_x_kernel<<<(Bn * Dn / 4 + 255) / 256, 256>>>(x);
    tw1_kernel<<<dim3(Dn / 32, 13, En), dim3(32, 8)>>>(W1);
    tw2_kernel<<<dim3(HP / 32, NW / 32, En), dim3(32, 8)>>>(W2);

    gemm1_mma<<<dim3(MAX_TILES, 5), 256, G1_SMEM>>>(b1);
    gemm2_mma<<<dim3(MAX_TILES, 4), 256, SMEM_SZ>>>(b2, out);
}

// round 8
// speedup vs baseline: 1.2475x; 1.2475x over previous
#include <cuda_runtime.h>
#include <cuda_fp16.h>
#include <cstdint>

// Problem constants
constexpr int Bn = 8192;   // batch
constexpr int Dn = 1024;   // input dim (K1)
constexpr int Hn = 400;    // hidden
constexpr int Ln = 256;    // half output
constexpr int En = 16;     // experts
constexpr int K2n = 512;   // 2L (N of GEMM2)
constexpr int HP = 416;    // hidden padded to 13*32 (K of GEMM2)
constexpr int NW = 512;    // padded N rows for transposed weights

#define TILE_M 128
#define MAX_TILES 80       // >= worst case sum ceil(ci/128) = 79
#define NT1 80             // GEMM1 N-tile (5 tiles * 80 = 400 exact)

// ================= device scratch (zero-init, no allocs) =================
__device__ int   g_idx_sorted[Bn + TILE_M];
__device__ int   g_tile_expert[MAX_TILES];
__device__ int   g_tile_rowstart[MAX_TILES];
__device__ int   g_tile_rows[MAX_TILES];

// fp16 buffers, uint4 for 16B alignment
__device__ uint4 g_x_hi[(size_t)Bn * Dn / 8];              // [Bn][1024] fp16
__device__ uint4 g_x_lo[(size_t)Bn * Dn / 8];              // activation residual
__device__ uint4 g_w1t[(size_t)En * NW * Dn / 8];          // [E][512][1024] (n,k) fp16
__device__ uint4 g_w2t[(size_t)En * NW * HP / 8];          // [E][512][416] (n,k) fp16
__device__ uint4 g_h1_hi[(size_t)(Bn + TILE_M) * HP / 8];  // [rows][416] fp16
__device__ uint4 g_h1_lo[(size_t)(Bn + TILE_M) * HP / 8];

// ================= helpers =================
__device__ __forceinline__ uint32_t smem_u32(const void* p) {
    uint32_t a;
    asm("{ .reg .u64 t; cvta.to.shared.u64 t, %1; cvt.u32.u64 %0, t; }" : "=r"(a) : "l"(p));
    return a;
}

#define CP16(dst_u32, src_ptr) \
    asm volatile("cp.async.cg.shared.global [%0], [%1], 16;" :: "r"(dst_u32), "l"(src_ptr))
#define CP_COMMIT() asm volatile("cp.async.commit_group;" ::: "memory")
#define CP_WAIT1()  asm volatile("cp.async.wait_group 1;" ::: "memory")
#define CP_WAIT0()  asm volatile("cp.async.wait_group 0;" ::: "memory")

__device__ __forceinline__ void mma16816(float* d, const uint32_t* a, const uint32_t* b) {
    asm volatile(
        "mma.sync.aligned.m16n8k16.row.col.f32.f16.f16.f32 "
        "{%0,%1,%2,%3}, {%4,%5,%6,%7}, {%8,%9}, {%0,%1,%2,%3};"
        : "+f"(d[0]), "+f"(d[1]), "+f"(d[2]), "+f"(d[3])
        : "r"(a[0]), "r"(a[1]), "r"(a[2]), "r"(a[3]), "r"(b[0]), "r"(b[1]));
}

// fp16 hi/lo split of two floats, packed
__device__ __forceinline__ void hsplit2(float v0, float v1, uint32_t& hi, uint32_t& lo) {
    __half h0 = __float2half(v0);
    __half h1 = __float2half(v1);
    __half l0 = __float2half(v0 - __half2float(h0));
    __half l1 = __float2half(v1 - __half2float(h1));
    __half2 ph; ph.x = h0; ph.y = h1;
    __half2 pl; pl.x = l0; pl.y = l1;
    hi = *reinterpret_cast<uint32_t*>(&ph);
    lo = *reinterpret_cast<uint32_t*>(&pl);
}

// ================= fused sort kernel (single block) =================
__global__ __launch_bounds__(1024) void sort_kernel(const void* __restrict__ ai) {
    __shared__ int s_cnt[En], s_off[En], s_cur[En];
    __shared__ int s_is64;
    int t = threadIdx.x;
    if (t < En) { s_cnt[t] = 0; s_cur[t] = 0; }
    if (t == 0) s_is64 = 1;
    if (t < TILE_M) g_idx_sorted[Bn + t] = 0;
    __syncthreads();

    const long long* a64 = (const long long*)ai;
    for (int i = t; i < Bn / 2; i += 1024) {
        long long v = a64[i];
        if (v < 0 || v >= En) s_is64 = 0;
    }
    __syncthreads();
    int is64 = s_is64;

    int vals[8];
#pragma unroll
    for (int j = 0; j < 8; j++) {
        int i = t + j * 1024;
        int v = is64 ? (int)a64[i] : ((const int*)ai)[i];
        vals[j] = v;
        atomicAdd(&s_cnt[v], 1);
    }
    __syncthreads();

    if (t == 0) {
        int off = 0, tb = 0;
        for (int e = 0; e < En; e++) {
            s_off[e] = off;
            int nt = (s_cnt[e] + TILE_M - 1) / TILE_M;
            for (int k = 0; k < nt; k++) {
                g_tile_expert[tb + k]   = e;
                g_tile_rowstart[tb + k] = off + k * TILE_M;
                int rem = s_cnt[e] - k * TILE_M;
                g_tile_rows[tb + k]     = rem < TILE_M ? rem : TILE_M;
            }
            tb += nt;
            off += s_cnt[e];
        }
        for (; tb < MAX_TILES; tb++) g_tile_rows[tb] = 0;
    }
    __syncthreads();

#pragma unroll
    for (int j = 0; j < 8; j++) {
        int i = t + j * 1024;
        int e = vals[j];
        int pos = atomicAdd(&s_cur[e], 1);
        g_idx_sorted[s_off[e] + pos] = i;
    }
}

// ================= conversions =================
// x fp16 split + h1 pad-column zeroing (cols 400..415)
__global__ void split_x_kernel(const float* __restrict__ x) {
    int i = blockIdx.x * blockDim.x + threadIdx.x;
    if (i < Bn * Dn / 4) {
        float4 v = reinterpret_cast<const float4*>(x)[i];
        uint32_t h0, l0, h1, l1;
        hsplit2(v.x, v.y, h0, l0);
        hsplit2(v.z, v.w, h1, l1);
        uint32_t* xh = reinterpret_cast<uint32_t*>(g_x_hi);
        uint32_t* xl = reinterpret_cast<uint32_t*>(g_x_lo);
        xh[i * 2] = h0; xh[i * 2 + 1] = h1;
        xl[i * 2] = l0; xl[i * 2 + 1] = l1;
    }
    if (i < (Bn + TILE_M) * 8) {
        int row = i >> 3, c = i & 7;
        uint32_t* h1h = reinterpret_cast<uint32_t*>(g_h1_hi);
        uint32_t* h1l = reinterpret_cast<uint32_t*>(g_h1_lo);
        size_t o = (size_t)row * (HP / 2) + 200 + c;
        h1h[o] = 0;
        h1l[o] = 0;
    }
}

// W1 [E][1024(k)][400(n)] -> fp16 [E][512(n)][1024(k)], rows 0..415 (n>=400 zero)
__global__ void tw1_kernel(const float* __restrict__ W1) {
    __shared__ float t[32][33];
    int e = blockIdx.z, k0 = blockIdx.x * 32, n0 = blockIdx.y * 32;
    int tx = threadIdx.x, ty = threadIdx.y;   // 32 x 8
    const float* W = W1 + (size_t)e * Dn * Hn;
#pragma unroll
    for (int i = 0; i < 32; i += 8) {
        int k = k0 + ty + i, n = n0 + tx;
        t[ty + i][tx] = (n < Hn) ? W[(size_t)k * Hn + n] : 0.f;
    }
    __syncthreads();
    __half* wh = reinterpret_cast<__half*>(g_w1t);
#pragma unroll
    for (int i = 0; i < 32; i += 8) {
        int n = n0 + ty + i, k = k0 + tx;
        wh[((size_t)e * NW + n) * Dn + k] = __float2half(t[tx][ty + i]);
    }
}

// W2 [E][400(k)][512(n)] -> fp16 [E][512(n)][416(k)], k>=400 zero
__global__ void tw2_kernel(const float* __restrict__ W2) {
    __shared__ float t[32][33];
    int e = blockIdx.z, k0 = blockIdx.x * 32, n0 = blockIdx.y * 32;
    int tx = threadIdx.x, ty = threadIdx.y;
    const float* W = W2 + (size_t)e * Hn * K2n;
#pragma unroll
    for (int i = 0; i < 32; i += 8) {
        int k = k0 + ty + i, n = n0 + tx;
        t[ty + i][tx] = (k < Hn) ? W[(size_t)k * K2n + n] : 0.f;
    }
    __syncthreads();
    __half* wh = reinterpret_cast<__half*>(g_w2t);
#pragma unroll
    for (int i = 0; i < 32; i += 8) {
        int n = n0 + ty + i, k = k0 + tx;
        wh[((size_t)e * NW + n) * HP + k] = __float2half(t[tx][ty + i]);
    }
}

// ================= GEMM1: fp16 2-pass, tile 128x80 =================
// smem: [0,512) idx, [512,896) bias, [1024..) two stages
// stage (80B row stride): Ahi r0-127 @0, Alo @10240, B @20480 (80 rows)
#define G1_STAGE 26880
#define G1_SMEM  (1024 + 2 * G1_STAGE)

__global__ __launch_bounds__(256) void gemm1_mma(const float* __restrict__ b1) {
    int bt = blockIdx.x;
    int rows = g_tile_rows[bt];
    if (rows == 0) return;
    int e  = g_tile_expert[bt];
    int rs = g_tile_rowstart[bt];
    int colbase = blockIdx.y * NT1;

    extern __shared__ char smem[];
    uint32_t sb = smem_u32(smem);
    int tid = threadIdx.x;
    int wid = tid >> 5, lane = tid & 31;
    int wm = wid & 3, wn = wid >> 2;      // warps: 4 (M) x 2 (N); warp tile 32x40
    int tq = lane >> 2, tr = lane & 3;

    int* idx_s = reinterpret_cast<int*>(smem);
    float* bias_s = reinterpret_cast<float*>(smem + 512);
    if (tid < TILE_M) idx_s[tid] = g_idx_sorted[rs + tid];
    if (tid < NT1) bias_s[tid] = b1[e * Hn + colbase + tid];
    __syncthreads();

    const uint4* w1 = g_w1t + (size_t)e * NW * (Dn / 8);

    auto fill = [&](int stg, int kt) {
        uint32_t base = sb + 1024 + stg * G1_STAGE;
#pragma unroll
        for (int i = tid; i < 512; i += 256) {        // A hi/lo: 128 rows x 4 uint4
            int r = i >> 2, c4 = i & 3;
            uint32_t d = base + r * 80 + c4 * 16;
            size_t ao = (size_t)idx_s[r] * 128 + kt * 4 + c4;
            CP16(d,         g_x_hi + ao);
            CP16(d + 10240, g_x_lo + ao);
        }
#pragma unroll
        for (int i = tid; i < 320; i += 256) {        // B: 80 rows x 4 uint4
            int r = i >> 2, c4 = i & 3;
            uint32_t d = base + 20480 + r * 80 + c4 * 16;
            size_t bo = (size_t)(colbase + r) * 128 + kt * 4 + c4;
            CP16(d, w1 + bo);
        }
    };

    float acc[2][5][4];
#pragma unroll
    for (int mt = 0; mt < 2; mt++)
#pragma unroll
        for (int nt = 0; nt < 5; nt++)
#pragma unroll
            for (int j = 0; j < 4; j++) acc[mt][nt][j] = 0.f;

    fill(0, 0); CP_COMMIT();
    for (int it = 0; it < 32; it++) {
        if (it + 1 < 32) { fill((it + 1) & 1, it + 1); CP_COMMIT(); CP_WAIT1(); }
        else CP_WAIT0();
        __syncthreads();
        const char* st = smem + 1024 + (it & 1) * G1_STAGE;
#pragma unroll
        for (int ks = 0; ks < 2; ks++) {
            int kb = ks * 32 + tr * 4;
            uint32_t ah[2][4], al[2][4], bb[5][2];
#pragma unroll
            for (int mt = 0; mt < 2; mt++) {
                int r0 = wm * 32 + mt * 16 + tq;
                ah[mt][0] = *(const uint32_t*)(st + r0 * 80 + kb);
                ah[mt][1] = *(const uint32_t*)(st + (r0 + 8) * 80 + kb);
                ah[mt][2] = *(const uint32_t*)(st + r0 * 80 + kb + 16);
                ah[mt][3] = *(const uint32_t*)(st + (r0 + 8) * 80 + kb + 16);
                al[mt][0] = *(const uint32_t*)(st + 10240 + r0 * 80 + kb);
                al[mt][1] = *(const uint32_t*)(st + 10240 + (r0 + 8) * 80 + kb);
                al[mt][2] = *(const uint32_t*)(st + 10240 + r0 * 80 + kb + 16);
                al[mt][3] = *(const uint32_t*)(st + 10240 + (r0 + 8) * 80 + kb + 16);
            }
#pragma unroll
            for (int nt = 0; nt < 5; nt++) {
                int n = wn * 40 + nt * 8 + tq;
                bb[nt][0] = *(const uint32_t*)(st + 20480 + n * 80 + kb);
                bb[nt][1] = *(const uint32_t*)(st + 20480 + n * 80 + kb + 16);
            }
#pragma unroll
            for (int mt = 0; mt < 2; mt++)
#pragma unroll
                for (int nt = 0; nt < 5; nt++) {
                    mma16816(acc[mt][nt], ah[mt], bb[nt]);   // hi pass
                    mma16816(acc[mt][nt], al[mt], bb[nt]);   // residual pass
                }
        }
        __syncthreads();
    }

    // epilogue: bias + relu + fp16 split -> h1
    uint32_t* h1h = reinterpret_cast<uint32_t*>(g_h1_hi);
    uint32_t* h1l = reinterpret_cast<uint32_t*>(g_h1_lo);
#pragma unroll
    for (int mt = 0; mt < 2; mt++) {
        int r0 = wm * 32 + mt * 16 + tq;
#pragma unroll
        for (int nt = 0; nt < 5; nt++) {
            int c = wn * 40 + nt * 8 + tr * 2;
            int gcol = colbase + c;
#pragma unroll
            for (int half = 0; half < 2; half++) {
                int r = r0 + half * 8;
                if (r >= rows) continue;
                float v0 = fmaxf(acc[mt][nt][half * 2]     + bias_s[c], 0.f);
                float v1 = fmaxf(acc[mt][nt][half * 2 + 1] + bias_s[c + 1], 0.f);
                uint32_t hi, lo;
                hsplit2(v0, v1, hi, lo);
                size_t o = ((size_t)(rs + r) * HP + gcol) >> 1;
                h1h[o] = hi;
                h1l[o] = lo;
            }
        }
    }
}

// ================= GEMM2: fp16 2-pass, tile 128x128, K=416 =================
// stage: Ahi@0 (128r), Alo@10240, B@20480 (128r) -> 30720B
#define STAGE_SZ 30720
#define SMEM_SZ  (1024 + 2 * STAGE_SZ)

__global__ __launch_bounds__(256) void gemm2_mma(const float* __restrict__ b2,
                                                 float* __restrict__ out) {
    int bt = blockIdx.x;
    int rows = g_tile_rows[bt];
    if (rows == 0) return;
    int e  = g_tile_expert[bt];
    int rs = g_tile_rowstart[bt];
    int colbase = blockIdx.y * 128;

    extern __shared__ char smem[];
    uint32_t sb = smem_u32(smem);
    int tid = threadIdx.x;
    int wid = tid >> 5, lane = tid & 31;
    int wm = wid & 3, wn = wid >> 2;
    int tq = lane >> 2, tr = lane & 3;

    int* idx_s = reinterpret_cast<int*>(smem);
    float* bias_s = reinterpret_cast<float*>(smem + 512);
    if (tid < TILE_M) idx_s[tid] = g_idx_sorted[rs + tid];
    if (tid < 128) bias_s[tid] = b2[e * K2n + colbase + tid];
    __syncthreads();

    const uint4* w2 = g_w2t + (size_t)e * NW * (HP / 8);

    auto fill = [&](int stg, int kt) {
        uint32_t base = sb + 1024 + stg * STAGE_SZ;
#pragma unroll
        for (int i = tid; i < 512; i += 256) {
            int r = i >> 2, c4 = i & 3;
            uint32_t dA = base + r * 80 + c4 * 16;
            size_t ao = (size_t)(rs + r) * (HP / 8) + kt * 4 + c4;
            CP16(dA,         g_h1_hi + ao);
            CP16(dA + 10240, g_h1_lo + ao);
            uint32_t dB = base + 20480 + r * 80 + c4 * 16;
            size_t bo = (size_t)(colbase + r) * (HP / 8) + kt * 4 + c4;
            CP16(dB, w2 + bo);
        }
    };

    float acc[2][8][4];
#pragma unroll
    for (int mt = 0; mt < 2; mt++)
#pragma unroll
        for (int nt = 0; nt < 8; nt++)
#pragma unroll
            for (int j = 0; j < 4; j++) acc[mt][nt][j] = 0.f;

    fill(0, 0); CP_COMMIT();
    for (int it = 0; it < 13; it++) {
        if (it + 1 < 13) { fill((it + 1) & 1, it + 1); CP_COMMIT(); CP_WAIT1(); }
        else CP_WAIT0();
        __syncthreads();
        const char* st = smem + 1024 + (it & 1) * STAGE_SZ;
#pragma unroll
        for (int ks = 0; ks < 2; ks++) {
            const char* As = st;
            const char* Bs = st + 20480;
            int kb = ks * 32 + tr * 4;
            uint32_t ah[2][4], al[2][4], bb[8][2];
#pragma unroll
            for (int mt = 0; mt < 2; mt++) {
                int r0 = wm * 32 + mt * 16 + tq;
                ah[mt][0] = *(const uint32_t*)(As + r0 * 80 + kb);
                ah[mt][1] = *(const uint32_t*)(As + (r0 + 8) * 80 + kb);
                ah[mt][2] = *(const uint32_t*)(As + r0 * 80 + kb + 16);
                ah[mt][3] = *(const uint32_t*)(As + (r0 + 8) * 80 + kb + 16);
                al[mt][0] = *(const uint32_t*)(As + 10240 + r0 * 80 + kb);
                al[mt][1] = *(const uint32_t*)(As + 10240 + (r0 + 8) * 80 + kb);
                al[mt][2] = *(const uint32_t*)(As + 10240 + r0 * 80 + kb + 16);
                al[mt][3] = *(const uint32_t*)(As + 10240 + (r0 + 8) * 80 + kb + 16);
            }
#pragma unroll
            for (int nt = 0; nt < 8; nt++) {
                int n = wn * 64 + nt * 8 + tq;
                bb[nt][0] = *(const uint32_t*)(Bs + n * 80 + kb);
                bb[nt][1] = *(const uint32_t*)(Bs + n * 80 + kb + 16);
            }
#pragma unroll
            for (int mt = 0; mt < 2; mt++)
#pragma unroll
                for (int nt = 0; nt < 8; nt++) {
                    mma16816(acc[mt][nt], ah[mt], bb[nt]);
                    mma16816(acc[mt][nt], al[mt], bb[nt]);
                }
        }
        __syncthreads();
    }

#pragma unroll
    for (int mt = 0; mt < 2; mt++) {
        int r0 = wm * 32 + mt * 16 + tq;
#pragma unroll
        for (int nt = 0; nt < 8; nt++) {
            int c = wn * 64 + nt * 8 + tr * 2;
            int gcol = colbase + c;
#pragma unroll
            for (int half = 0; half < 2; half++) {
                int r = r0 + half * 8;
                if (r >= rows) continue;
                int b = idx_s[r];
                float2 v;
                v.x = acc[mt][nt][half * 2]     + bias_s[c];
                v.y = acc[mt][nt][half * 2 + 1] + bias_s[c + 1];
                float* dst = (gcol < Ln)
                    ? out + (size_t)b * Ln + gcol
                    : out + (size_t)Bn * Ln + (size_t)b * Ln + (gcol - Ln);
                *reinterpret_cast<float2*>(dst) = v;
            }
        }
    }
}

// ================= launch =================
extern "C" void kernel_launch(void* const* d_in, const int* in_sizes, int n_in,
                              void* d_out, int out_size) {
    const float* x  = (const float*)d_in[0];
    const void*  ai = d_in[1];
    const float* W1 = (const float*)d_in[2];
    const float* b1 = (const float*)d_in[3];
    const float* W2 = (const float*)d_in[4];
    const float* b2 = (const float*)d_in[5];
    float* out = (float*)d_out;

    cudaFuncSetAttribute(gemm1_mma, cudaFuncAttributeMaxDynamicSharedMemorySize, G1_SMEM);
    cudaFuncSetAttribute(gemm2_mma, cudaFuncAttributeMaxDynamicSharedMemorySize, SMEM_SZ);

    sort_kernel<<<1, 1024>>>(ai);
    split_x_kernel<<<(Bn * Dn / 4 + 255) / 256, 256>>>(x);
    tw1_kernel<<<dim3(Dn / 32, 13, En), dim3(32, 8)>>>(W1);
    tw2_kernel<<<dim3(HP / 32, NW / 32, En), dim3(32, 8)>>>(W2);

    gemm1_mma<<<dim3(MAX_TILES, 5), 256, G1_SMEM>>>(b1);
    gemm2_mma<<<dim3(MAX_TILES, 4), 256, SMEM_SZ>>>(b2, out);
}

// round 9
// speedup vs baseline: 1.6965x; 1.3599x over previous
#include <cuda_runtime.h>
#include <cuda_fp16.h>
#include <cstdint>

// Problem constants
constexpr int Bn = 8192;   // batch
constexpr int Dn = 1024;   // input dim (K1)
constexpr int Hn = 400;    // hidden
constexpr int Ln = 256;    // half output
constexpr int En = 16;     // experts
constexpr int K2n = 512;   // 2L (N of GEMM2)
constexpr int HP = 416;    // hidden padded to 13*32 (K of GEMM2)
constexpr int NW = 512;    // padded N rows for transposed weights

#define TILE_M 128
#define MAX_TILES 80       // >= worst case sum ceil(ci/128) = 79
#define NT1 80             // GEMM1 N-tile (5 tiles * 80 = 400 exact)

// ================= device scratch (zero-init, no allocs) =================
__device__ int   g_idx_sorted[Bn + TILE_M];
__device__ int   g_tile_expert[MAX_TILES];
__device__ int   g_tile_rowstart[MAX_TILES];
__device__ int   g_tile_rows[MAX_TILES];

// fp16 buffers, uint4 for 16B alignment
__device__ uint4 g_x[(size_t)Bn * Dn / 8];                 // [Bn][1024] fp16
__device__ uint4 g_w1t[(size_t)En * NW * Dn / 8];          // [E][512][1024] (n,k) fp16
__device__ uint4 g_w2t[(size_t)En * NW * HP / 8];          // [E][512][416] (n,k) fp16
__device__ uint4 g_h1[(size_t)(Bn + TILE_M) * HP / 8];     // [rows][416] fp16

// ================= helpers =================
__device__ __forceinline__ uint32_t smem_u32(const void* p) {
    uint32_t a;
    asm("{ .reg .u64 t; cvta.to.shared.u64 t, %1; cvt.u32.u64 %0, t; }" : "=r"(a) : "l"(p));
    return a;
}

#define CP16(dst_u32, src_ptr) \
    asm volatile("cp.async.cg.shared.global [%0], [%1], 16;" :: "r"(dst_u32), "l"(src_ptr))
#define CP_COMMIT() asm volatile("cp.async.commit_group;" ::: "memory")
#define CP_WAIT1()  asm volatile("cp.async.wait_group 1;" ::: "memory")
#define CP_WAIT0()  asm volatile("cp.async.wait_group 0;" ::: "memory")

__device__ __forceinline__ void mma16816(float* d, const uint32_t* a, const uint32_t* b) {
    asm volatile(
        "mma.sync.aligned.m16n8k16.row.col.f32.f16.f16.f32 "
        "{%0,%1,%2,%3}, {%4,%5,%6,%7}, {%8,%9}, {%0,%1,%2,%3};"
        : "+f"(d[0]), "+f"(d[1]), "+f"(d[2]), "+f"(d[3])
        : "r"(a[0]), "r"(a[1]), "r"(a[2]), "r"(a[3]), "r"(b[0]), "r"(b[1]));
}

__device__ __forceinline__ uint32_t hpack2(float v0, float v1) {
    __half2 p;
    p.x = __float2half(v0);
    p.y = __float2half(v1);
    return *reinterpret_cast<uint32_t*>(&p);
}

// ================= fused sort kernel (single block) =================
__global__ __launch_bounds__(1024) void sort_kernel(const void* __restrict__ ai) {
    __shared__ int s_cnt[En], s_off[En], s_cur[En];
    __shared__ int s_is64;
    int t = threadIdx.x;
    if (t < En) { s_cnt[t] = 0; s_cur[t] = 0; }
    if (t == 0) s_is64 = 1;
    if (t < TILE_M) g_idx_sorted[Bn + t] = 0;
    __syncthreads();

    const long long* a64 = (const long long*)ai;
    for (int i = t; i < Bn / 2; i += 1024) {
        long long v = a64[i];
        if (v < 0 || v >= En) s_is64 = 0;
    }
    __syncthreads();
    int is64 = s_is64;

    int vals[8];
#pragma unroll
    for (int j = 0; j < 8; j++) {
        int i = t + j * 1024;
        int v = is64 ? (int)a64[i] : ((const int*)ai)[i];
        vals[j] = v;
        atomicAdd(&s_cnt[v], 1);
    }
    __syncthreads();

    if (t == 0) {
        int off = 0, tb = 0;
        for (int e = 0; e < En; e++) {
            s_off[e] = off;
            int nt = (s_cnt[e] + TILE_M - 1) / TILE_M;
            for (int k = 0; k < nt; k++) {
                g_tile_expert[tb + k]   = e;
                g_tile_rowstart[tb + k] = off + k * TILE_M;
                int rem = s_cnt[e] - k * TILE_M;
                g_tile_rows[tb + k]     = rem < TILE_M ? rem : TILE_M;
            }
            tb += nt;
            off += s_cnt[e];
        }
        for (; tb < MAX_TILES; tb++) g_tile_rows[tb] = 0;
    }
    __syncthreads();

#pragma unroll
    for (int j = 0; j < 8; j++) {
        int i = t + j * 1024;
        int e = vals[j];
        int pos = atomicAdd(&s_cur[e], 1);
        g_idx_sorted[s_off[e] + pos] = i;
    }
}

// ================= conversions =================
// x fp16 + h1 pad-column zeroing (cols 400..415)
__global__ void split_x_kernel(const float* __restrict__ x) {
    int i = blockIdx.x * blockDim.x + threadIdx.x;
    if (i < Bn * Dn / 4) {
        float4 v = reinterpret_cast<const float4*>(x)[i];
        uint2 p;
        p.x = hpack2(v.x, v.y);
        p.y = hpack2(v.z, v.w);
        reinterpret_cast<uint2*>(g_x)[i] = p;
    }
    if (i < (Bn + TILE_M) * 8) {
        int row = i >> 3, c = i & 7;
        uint32_t* h1 = reinterpret_cast<uint32_t*>(g_h1);
        h1[(size_t)row * (HP / 2) + 200 + c] = 0;
    }
}

// W1 [E][1024(k)][400(n)] -> fp16 [E][512(n)][1024(k)], rows 0..415 (n>=400 zero)
__global__ void tw1_kernel(const float* __restrict__ W1) {
    __shared__ float t[32][33];
    int e = blockIdx.z, k0 = blockIdx.x * 32, n0 = blockIdx.y * 32;
    int tx = threadIdx.x, ty = threadIdx.y;   // 32 x 8
    const float* W = W1 + (size_t)e * Dn * Hn;
#pragma unroll
    for (int i = 0; i < 32; i += 8) {
        int k = k0 + ty + i, n = n0 + tx;
        t[ty + i][tx] = (n < Hn) ? W[(size_t)k * Hn + n] : 0.f;
    }
    __syncthreads();
    __half* wh = reinterpret_cast<__half*>(g_w1t);
#pragma unroll
    for (int i = 0; i < 32; i += 8) {
        int n = n0 + ty + i, k = k0 + tx;
        wh[((size_t)e * NW + n) * Dn + k] = __float2half(t[tx][ty + i]);
    }
}

// W2 [E][400(k)][512(n)] -> fp16 [E][512(n)][416(k)], k>=400 zero
__global__ void tw2_kernel(const float* __restrict__ W2) {
    __shared__ float t[32][33];
    int e = blockIdx.z, k0 = blockIdx.x * 32, n0 = blockIdx.y * 32;
    int tx = threadIdx.x, ty = threadIdx.y;
    const float* W = W2 + (size_t)e * Hn * K2n;
#pragma unroll
    for (int i = 0; i < 32; i += 8) {
        int k = k0 + ty + i, n = n0 + tx;
        t[ty + i][tx] = (k < Hn) ? W[(size_t)k * K2n + n] : 0.f;
    }
    __syncthreads();
    __half* wh = reinterpret_cast<__half*>(g_w2t);
#pragma unroll
    for (int i = 0; i < 32; i += 8) {
        int n = n0 + ty + i, k = k0 + tx;
        wh[((size_t)e * NW + n) * HP + k] = __float2half(t[tx][ty + i]);
    }
}

// ================= GEMM1: fp16 single-pass, tile 128x80 =================
// smem: [0,512) idx, [512,896) bias, [1024..) two stages
// stage (80B row stride): A r0-127 @0 (10240B), B @10240 (80 rows, 6400B)
#define G1_STAGE 16640
#define G1_SMEM  (1024 + 2 * G1_STAGE)

__global__ __launch_bounds__(256) void gemm1_mma(const float* __restrict__ b1) {
    int bt = blockIdx.x;
    int rows = g_tile_rows[bt];
    if (rows == 0) return;
    int e  = g_tile_expert[bt];
    int rs = g_tile_rowstart[bt];
    int colbase = blockIdx.y * NT1;

    extern __shared__ char smem[];
    uint32_t sb = smem_u32(smem);
    int tid = threadIdx.x;
    int wid = tid >> 5, lane = tid & 31;
    int wm = wid & 3, wn = wid >> 2;      // warps: 4 (M) x 2 (N); warp tile 32x40
    int tq = lane >> 2, tr = lane & 3;

    int* idx_s = reinterpret_cast<int*>(smem);
    float* bias_s = reinterpret_cast<float*>(smem + 512);
    if (tid < TILE_M) idx_s[tid] = g_idx_sorted[rs + tid];
    if (tid < NT1) bias_s[tid] = b1[e * Hn + colbase + tid];
    __syncthreads();

    const uint4* w1 = g_w1t + (size_t)e * NW * (Dn / 8);

    auto fill = [&](int stg, int kt) {
        uint32_t base = sb + 1024 + stg * G1_STAGE;
#pragma unroll
        for (int i = tid; i < 512; i += 256) {        // A: 128 rows x 4 uint4
            int r = i >> 2, c4 = i & 3;
            uint32_t d = base + r * 80 + c4 * 16;
            CP16(d, g_x + (size_t)idx_s[r] * 128 + kt * 4 + c4);
        }
#pragma unroll
        for (int i = tid; i < 320; i += 256) {        // B: 80 rows x 4 uint4
            int r = i >> 2, c4 = i & 3;
            uint32_t d = base + 10240 + r * 80 + c4 * 16;
            CP16(d, w1 + (size_t)(colbase + r) * 128 + kt * 4 + c4);
        }
    };

    float acc[2][5][4];
#pragma unroll
    for (int mt = 0; mt < 2; mt++)
#pragma unroll
        for (int nt = 0; nt < 5; nt++)
#pragma unroll
            for (int j = 0; j < 4; j++) acc[mt][nt][j] = 0.f;

    fill(0, 0); CP_COMMIT();
    for (int it = 0; it < 32; it++) {
        if (it + 1 < 32) { fill((it + 1) & 1, it + 1); CP_COMMIT(); CP_WAIT1(); }
        else CP_WAIT0();
        __syncthreads();
        const char* st = smem + 1024 + (it & 1) * G1_STAGE;
#pragma unroll
        for (int ks = 0; ks < 2; ks++) {
            int kb = ks * 32 + tr * 4;
            uint32_t ah[2][4], bb[5][2];
#pragma unroll
            for (int mt = 0; mt < 2; mt++) {
                int r0 = wm * 32 + mt * 16 + tq;
                ah[mt][0] = *(const uint32_t*)(st + r0 * 80 + kb);
                ah[mt][1] = *(const uint32_t*)(st + (r0 + 8) * 80 + kb);
                ah[mt][2] = *(const uint32_t*)(st + r0 * 80 + kb + 16);
                ah[mt][3] = *(const uint32_t*)(st + (r0 + 8) * 80 + kb + 16);
            }
#pragma unroll
            for (int nt = 0; nt < 5; nt++) {
                int n = wn * 40 + nt * 8 + tq;
                bb[nt][0] = *(const uint32_t*)(st + 10240 + n * 80 + kb);
                bb[nt][1] = *(const uint32_t*)(st + 10240 + n * 80 + kb + 16);
            }
#pragma unroll
            for (int mt = 0; mt < 2; mt++)
#pragma unroll
                for (int nt = 0; nt < 5; nt++)
                    mma16816(acc[mt][nt], ah[mt], bb[nt]);
        }
        __syncthreads();
    }

    // epilogue: bias + relu -> fp16 h1
    uint32_t* h1 = reinterpret_cast<uint32_t*>(g_h1);
#pragma unroll
    for (int mt = 0; mt < 2; mt++) {
        int r0 = wm * 32 + mt * 16 + tq;
#pragma unroll
        for (int nt = 0; nt < 5; nt++) {
            int c = wn * 40 + nt * 8 + tr * 2;
            int gcol = colbase + c;
#pragma unroll
            for (int half = 0; half < 2; half++) {
                int r = r0 + half * 8;
                if (r >= rows) continue;
                float v0 = fmaxf(acc[mt][nt][half * 2]     + bias_s[c], 0.f);
                float v1 = fmaxf(acc[mt][nt][half * 2 + 1] + bias_s[c + 1], 0.f);
                h1[((size_t)(rs + r) * HP + gcol) >> 1] = hpack2(v0, v1);
            }
        }
    }
}

// ================= GEMM2: fp16 single-pass, tile 128x128, K=416 =================
// stage: A@0 (128r, 10240B), B@10240 (128r, 10240B)
#define STAGE_SZ 20480
#define SMEM_SZ  (1024 + 2 * STAGE_SZ)

__global__ __launch_bounds__(256) void gemm2_mma(const float* __restrict__ b2,
                                                 float* __restrict__ out) {
    int bt = blockIdx.x;
    int rows = g_tile_rows[bt];
    if (rows == 0) return;
    int e  = g_tile_expert[bt];
    int rs = g_tile_rowstart[bt];
    int colbase = blockIdx.y * 128;

    extern __shared__ char smem[];
    uint32_t sb = smem_u32(smem);
    int tid = threadIdx.x;
    int wid = tid >> 5, lane = tid & 31;
    int wm = wid & 3, wn = wid >> 2;
    int tq = lane >> 2, tr = lane & 3;

    int* idx_s = reinterpret_cast<int*>(smem);
    float* bias_s = reinterpret_cast<float*>(smem + 512);
    if (tid < TILE_M) idx_s[tid] = g_idx_sorted[rs + tid];
    if (tid < 128) bias_s[tid] = b2[e * K2n + colbase + tid];
    __syncthreads();

    const uint4* w2 = g_w2t + (size_t)e * NW * (HP / 8);

    auto fill = [&](int stg, int kt) {
        uint32_t base = sb + 1024 + stg * STAGE_SZ;
#pragma unroll
        for (int i = tid; i < 512; i += 256) {
            int r = i >> 2, c4 = i & 3;
            uint32_t dA = base + r * 80 + c4 * 16;
            CP16(dA, g_h1 + (size_t)(rs + r) * (HP / 8) + kt * 4 + c4);
            uint32_t dB = base + 10240 + r * 80 + c4 * 16;
            CP16(dB, w2 + (size_t)(colbase + r) * (HP / 8) + kt * 4 + c4);
        }
    };

    float acc[2][8][4];
#pragma unroll
    for (int mt = 0; mt < 2; mt++)
#pragma unroll
        for (int nt = 0; nt < 8; nt++)
#pragma unroll
            for (int j = 0; j < 4; j++) acc[mt][nt][j] = 0.f;

    fill(0, 0); CP_COMMIT();
    for (int it = 0; it < 13; it++) {
        if (it + 1 < 13) { fill((it + 1) & 1, it + 1); CP_COMMIT(); CP_WAIT1(); }
        else CP_WAIT0();
        __syncthreads();
        const char* st = smem + 1024 + (it & 1) * STAGE_SZ;
#pragma unroll
        for (int ks = 0; ks < 2; ks++) {
            int kb = ks * 32 + tr * 4;
            uint32_t ah[2][4], bb[8][2];
#pragma unroll
            for (int mt = 0; mt < 2; mt++) {
                int r0 = wm * 32 + mt * 16 + tq;
                ah[mt][0] = *(const uint32_t*)(st + r0 * 80 + kb);
                ah[mt][1] = *(const uint32_t*)(st + (r0 + 8) * 80 + kb);
                ah[mt][2] = *(const uint32_t*)(st + r0 * 80 + kb + 16);
                ah[mt][3] = *(const uint32_t*)(st + (r0 + 8) * 80 + kb + 16);
            }
#pragma unroll
            for (int nt = 0; nt < 8; nt++) {
                int n = wn * 64 + nt * 8 + tq;
                bb[nt][0] = *(const uint32_t*)(st + 10240 + n * 80 + kb);
                bb[nt][1] = *(const uint32_t*)(st + 10240 + n * 80 + kb + 16);
            }
#pragma unroll
            for (int mt = 0; mt < 2; mt++)
#pragma unroll
                for (int nt = 0; nt < 8; nt++)
                    mma16816(acc[mt][nt], ah[mt], bb[nt]);
        }
        __syncthreads();
    }

#pragma unroll
    for (int mt = 0; mt < 2; mt++) {
        int r0 = wm * 32 + mt * 16 + tq;
#pragma unroll
        for (int nt = 0; nt < 8; nt++) {
            int c = wn * 64 + nt * 8 + tr * 2;
            int gcol = colbase + c;
#pragma unroll
            for (int half = 0; half < 2; half++) {
                int r = r0 + half * 8;
                if (r >= rows) continue;
                int b = idx_s[r];
                float2 v;
                v.x = acc[mt][nt][half * 2]     + bias_s[c];
                v.y = acc[mt][nt][half * 2 + 1] + bias_s[c + 1];
                float* dst = (gcol < Ln)
                    ? out + (size_t)b * Ln + gcol
                    : out + (size_t)Bn * Ln + (size_t)b * Ln + (gcol - Ln);
                *reinterpret_cast<float2*>(dst) = v;
            }
        }
    }
}

// ================= launch =================
extern "C" void kernel_launch(void* const* d_in, const int* in_sizes, int n_in,
                              void* d_out, int out_size) {
    const float* x  = (const float*)d_in[0];
    const void*  ai = d_in[1];
    const float* W1 = (const float*)d_in[2];
    const float* b1 = (const float*)d_in[3];
    const float* W2 = (const float*)d_in[4];
    const float* b2 = (const float*)d_in[5];
    float* out = (float*)d_out;

    cudaFuncSetAttribute(gemm1_mma, cudaFuncAttributeMaxDynamicSharedMemorySize, G1_SMEM);
    cudaFuncSetAttribute(gemm2_mma, cudaFuncAttributeMaxDynamicSharedMemorySize, SMEM_SZ);

    sort_kernel<<<1, 1024>>>(ai);
    split_x_kernel<<<(Bn * Dn / 4 + 255) / 256, 256>>>(x);
    tw1_kernel<<<dim3(Dn / 32, 13, En), dim3(32, 8)>>>(W1);
    tw2_kernel<<<dim3(HP / 32, NW / 32, En), dim3(32, 8)>>>(W2);

    gemm1_mma<<<dim3(MAX_TILES, 5), 256, G1_SMEM>>>(b1);
    gemm2_mma<<<dim3(MAX_TILES, 4), 256, SMEM_SZ>>>(b2, out);
}

// round 11
// speedup vs baseline: 1.7732x; 1.0452x over previous
#include <cuda_runtime.h>
#include <cuda_fp16.h>
#include <cstdint>

// Problem constants
constexpr int Bn = 8192;   // batch
constexpr int Dn = 1024;   // input dim (K1)
constexpr int Hn = 400;    // hidden
constexpr int Ln = 256;    // half output
constexpr int En = 16;     // experts
constexpr int K2n = 512;   // 2L (N of GEMM2)
constexpr int HP = 416;    // hidden padded to 13*32 (K of GEMM2)
constexpr int NW = 512;    // padded N rows for transposed weights

#define TILE_M 128
#define MAX_TILES 80       // >= worst case sum ceil(ci/128) = 79
#define NT1 80             // GEMM1 N-tile (5 tiles * 80 = 400 exact)

// prep grid partition
#define PREP_SORT_BLOCKS   1
#define PREP_SPLIT_BLOCKS  (Bn * Dn / 4 / 256)          // 8192
#define PREP_TW1_BLOCKS    (32 * 13 * En)               // 6656
#define PREP_TW2_BLOCKS    (13 * 16 * En)               // 3328
#define PREP_GRID (PREP_SORT_BLOCKS + PREP_SPLIT_BLOCKS + PREP_TW1_BLOCKS + PREP_TW2_BLOCKS)

// ================= device scratch (zero-init, no allocs) =================
__device__ int   g_idx_sorted[Bn + TILE_M];
__device__ int   g_tile_expert[MAX_TILES];
__device__ int   g_tile_rowstart[MAX_TILES];
__device__ int   g_tile_rows[MAX_TILES];

// fp16 buffers, uint4 for 16B alignment
__device__ uint4 g_x[(size_t)Bn * Dn / 8];                 // [Bn][1024] fp16
__device__ uint4 g_w1t[(size_t)En * NW * Dn / 8];          // [E][512][1024] (n,k) fp16
__device__ uint4 g_w2t[(size_t)En * NW * HP / 8];          // [E][512][416] (n,k) fp16
__device__ uint4 g_h1[(size_t)(Bn + TILE_M) * HP / 8];     // [rows][416] fp16

// ================= helpers =================
__device__ __forceinline__ uint32_t smem_u32(const void* p) {
    uint32_t a;
    asm("{ .reg .u64 t; cvta.to.shared.u64 t, %1; cvt.u32.u64 %0, t; }" : "=r"(a) : "l"(p));
    return a;
}

#define CP16(dst_u32, src_ptr) \
    asm volatile("cp.async.cg.shared.global [%0], [%1], 16;" :: "r"(dst_u32), "l"(src_ptr))
#define CP_COMMIT() asm volatile("cp.async.commit_group;" ::: "memory")
#define CP_WAIT2()  asm volatile("cp.async.wait_group 2;" ::: "memory")
#define CP_WAIT1()  asm volatile("cp.async.wait_group 1;" ::: "memory")
#define CP_WAIT0()  asm volatile("cp.async.wait_group 0;" ::: "memory")

__device__ __forceinline__ void mma16816(float* d, const uint32_t* a, const uint32_t* b) {
    asm volatile(
        "mma.sync.aligned.m16n8k16.row.col.f32.f16.f16.f32 "
        "{%0,%1,%2,%3}, {%4,%5,%6,%7}, {%8,%9}, {%0,%1,%2,%3};"
        : "+f"(d[0]), "+f"(d[1]), "+f"(d[2]), "+f"(d[3])
        : "r"(a[0]), "r"(a[1]), "r"(a[2]), "r"(a[3]), "r"(b[0]), "r"(b[1]));
}

__device__ __forceinline__ uint32_t hpack2(float v0, float v1) {
    __half2 p;
    p.x = __float2half(v0);
    p.y = __float2half(v1);
    return *reinterpret_cast<uint32_t*>(&p);
}

// ================= fused prep kernel: sort | split_x | tw1 | tw2 =================
__global__ __launch_bounds__(256) void prep_kernel(const void* __restrict__ ai,
                                                   const float* __restrict__ x,
                                                   const float* __restrict__ W1,
                                                   const float* __restrict__ W2) {
    int blk = blockIdx.x;
    int t = threadIdx.x;

    if (blk == 0) {
        // ---- sort: init + detect + count + prefix + tile list + scatter ----
        __shared__ int s_cnt[En], s_off[En], s_cur[En];
        __shared__ int s_is64;
        if (t < En) { s_cnt[t] = 0; s_cur[t] = 0; }
        if (t == 0) s_is64 = 1;
        if (t < TILE_M) g_idx_sorted[Bn + t] = 0;
        __syncthreads();

        const long long* a64 = (const long long*)ai;
        for (int i = t; i < Bn / 2; i += 256) {
            long long v = a64[i];
            if (v < 0 || v >= En) s_is64 = 0;
        }
        __syncthreads();
        int is64 = s_is64;

        int vals[32];
#pragma unroll
        for (int j = 0; j < 32; j++) {
            int i = t + j * 256;
            int v = is64 ? (int)a64[i] : ((const int*)ai)[i];
            vals[j] = v;
            atomicAdd(&s_cnt[v], 1);
        }
        __syncthreads();

        if (t == 0) {
            int off = 0, tb = 0;
            for (int e = 0; e < En; e++) {
                s_off[e] = off;
                int nt = (s_cnt[e] + TILE_M - 1) / TILE_M;
                for (int k = 0; k < nt; k++) {
                    g_tile_expert[tb + k]   = e;
                    g_tile_rowstart[tb + k] = off + k * TILE_M;
                    int rem = s_cnt[e] - k * TILE_M;
                    g_tile_rows[tb + k]     = rem < TILE_M ? rem : TILE_M;
                }
                tb += nt;
                off += s_cnt[e];
            }
            for (; tb < MAX_TILES; tb++) g_tile_rows[tb] = 0;
        }
        __syncthreads();

#pragma unroll
        for (int j = 0; j < 32; j++) {
            int i = t + j * 256;
            int e = vals[j];
            int pos = atomicAdd(&s_cur[e], 1);
            g_idx_sorted[s_off[e] + pos] = i;
        }
        return;
    }

    if (blk < PREP_SORT_BLOCKS + PREP_SPLIT_BLOCKS) {
        // ---- split_x: x -> fp16, + h1 pad zeroing ----
        int i = (blk - PREP_SORT_BLOCKS) * 256 + t;
        float4 v = reinterpret_cast<const float4*>(x)[i];
        uint2 p;
        p.x = hpack2(v.x, v.y);
        p.y = hpack2(v.z, v.w);
        reinterpret_cast<uint2*>(g_x)[i] = p;
        if (i < (Bn + TILE_M) * 8) {
            int row = i >> 3, c = i & 7;
            reinterpret_cast<uint32_t*>(g_h1)[(size_t)row * (HP / 2) + 200 + c] = 0;
        }
        return;
    }

    __shared__ float ts[32][33];
    int tx = t & 31, ty = t >> 5;    // 32 x 8

    if (blk < PREP_SORT_BLOCKS + PREP_SPLIT_BLOCKS + PREP_TW1_BLOCKS) {
        // ---- tw1: W1 [E][1024(k)][400(n)] -> fp16 [E][512(n)][1024(k)], n tiles 0..12 ----
        int idx = blk - PREP_SORT_BLOCKS - PREP_SPLIT_BLOCKS;
        int k0 = (idx & 31) * 32;
        int n0 = ((idx >> 5) % 13) * 32;
        int e  = idx / (32 * 13);
        const float* W = W1 + (size_t)e * Dn * Hn;
#pragma unroll
        for (int i = 0; i < 32; i += 8) {
            int k = k0 + ty + i, n = n0 + tx;
            ts[ty + i][tx] = (n < Hn) ? W[(size_t)k * Hn + n] : 0.f;
        }
        __syncthreads();
        __half* wh = reinterpret_cast<__half*>(g_w1t);
#pragma unroll
        for (int i = 0; i < 32; i += 8) {
            int n = n0 + ty + i, k = k0 + tx;
            wh[((size_t)e * NW + n) * Dn + k] = __float2half(ts[tx][ty + i]);
        }
        return;
    }

    {
        // ---- tw2: W2 [E][400(k)][512(n)] -> fp16 [E][512(n)][416(k)] ----
        int idx = blk - PREP_SORT_BLOCKS - PREP_SPLIT_BLOCKS - PREP_TW1_BLOCKS;
        int k0 = (idx % 13) * 32;
        int n0 = ((idx / 13) & 15) * 32;
        int e  = idx / (13 * 16);
        const float* W = W2 + (size_t)e * Hn * K2n;
#pragma unroll
        for (int i = 0; i < 32; i += 8) {
            int k = k0 + ty + i, n = n0 + tx;
            ts[ty + i][tx] = (k < Hn) ? W[(size_t)k * K2n + n] : 0.f;
        }
        __syncthreads();
        __half* wh = reinterpret_cast<__half*>(g_w2t);
#pragma unroll
        for (int i = 0; i < 32; i += 8) {
            int n = n0 + ty + i, k = k0 + tx;
            wh[((size_t)e * NW + n) * HP + k] = __float2half(ts[tx][ty + i]);
        }
    }
}

// ================= GEMM1: fp16 single-pass, tile 128x80, 3-stage =================
// smem: [0,512) idx, [512,896) bias, [1024..) three stages
// stage (80B row stride): A r0-127 @0 (10240B), B @10240 (80 rows, 6400B)
#define G1_STAGE 16640
#define G1_SMEM  (1024 + 3 * G1_STAGE)

__global__ __launch_bounds__(256) void gemm1_mma(const float* __restrict__ b1) {
    int bt = blockIdx.x;
    int rows = g_tile_rows[bt];
    if (rows == 0) return;
    int e  = g_tile_expert[bt];
    int rs = g_tile_rowstart[bt];
    int colbase = blockIdx.y * NT1;

    extern __shared__ char smem[];
    uint32_t sb = smem_u32(smem);
    int tid = threadIdx.x;
    int wid = tid >> 5, lane = tid & 31;
    int wm = wid & 3, wn = wid >> 2;      // warps: 4 (M) x 2 (N); warp tile 32x40
    int tq = lane >> 2, tr = lane & 3;

    int* idx_s = reinterpret_cast<int*>(smem);
    float* bias_s = reinterpret_cast<float*>(smem + 512);
    if (tid < TILE_M) idx_s[tid] = g_idx_sorted[rs + tid];
    if (tid < NT1) bias_s[tid] = b1[e * Hn + colbase + tid];
    __syncthreads();

    const uint4* w1 = g_w1t + (size_t)e * NW * (Dn / 8);

    auto fill = [&](int stg, int kt) {
        uint32_t base = sb + 1024 + stg * G1_STAGE;
#pragma unroll
        for (int i = tid; i < 512; i += 256) {        // A: 128 rows x 4 uint4
            int r = i >> 2, c4 = i & 3;
            uint32_t d = base + r * 80 + c4 * 16;
            CP16(d, g_x + (size_t)idx_s[r] * 128 + kt * 4 + c4);
        }
#pragma unroll
        for (int i = tid; i < 320; i += 256) {        // B: 80 rows x 4 uint4
            int r = i >> 2, c4 = i & 3;
            uint32_t d = base + 10240 + r * 80 + c4 * 16;
            CP16(d, w1 + (size_t)(colbase + r) * 128 + kt * 4 + c4);
        }
    };

    float acc[2][5][4];
#pragma unroll
    for (int mt = 0; mt < 2; mt++)
#pragma unroll
        for (int nt = 0; nt < 5; nt++)
#pragma unroll
            for (int j = 0; j < 4; j++) acc[mt][nt][j] = 0.f;

    fill(0, 0); CP_COMMIT();
    fill(1, 1); CP_COMMIT();
    for (int it = 0; it < 32; it++) {
        if (it + 2 < 32) { fill((it + 2) % 3, it + 2); CP_COMMIT(); CP_WAIT2(); }
        else if (it + 1 < 32) CP_WAIT1();
        else CP_WAIT0();
        __syncthreads();
        const char* st = smem + 1024 + (it % 3) * G1_STAGE;
#pragma unroll
        for (int ks = 0; ks < 2; ks++) {
            int kb = ks * 32 + tr * 4;
            uint32_t ah[2][4], bb[5][2];
#pragma unroll
            for (int mt = 0; mt < 2; mt++) {
                int r0 = wm * 32 + mt * 16 + tq;
                ah[mt][0] = *(const uint32_t*)(st + r0 * 80 + kb);
                ah[mt][1] = *(const uint32_t*)(st + (r0 + 8) * 80 + kb);
                ah[mt][2] = *(const uint32_t*)(st + r0 * 80 + kb + 16);
                ah[mt][3] = *(const uint32_t*)(st + (r0 + 8) * 80 + kb + 16);
            }
#pragma unroll
            for (int nt = 0; nt < 5; nt++) {
                int n = wn * 40 + nt * 8 + tq;
                bb[nt][0] = *(const uint32_t*)(st + 10240 + n * 80 + kb);
                bb[nt][1] = *(const uint32_t*)(st + 10240 + n * 80 + kb + 16);
            }
#pragma unroll
            for (int mt = 0; mt < 2; mt++)
#pragma unroll
                for (int nt = 0; nt < 5; nt++)
                    mma16816(acc[mt][nt], ah[mt], bb[nt]);
        }
        __syncthreads();
    }

    // epilogue: bias + relu -> fp16 h1
    uint32_t* h1 = reinterpret_cast<uint32_t*>(g_h1);
#pragma unroll
    for (int mt = 0; mt < 2; mt++) {
        int r0 = wm * 32 + mt * 16 + tq;
#pragma unroll
        for (int nt = 0; nt < 5; nt++) {
            int c = wn * 40 + nt * 8 + tr * 2;
            int gcol = colbase + c;
#pragma unroll
            for (int half = 0; half < 2; half++) {
                int r = r0 + half * 8;
                if (r >= rows) continue;
                float v0 = fmaxf(acc[mt][nt][half * 2]     + bias_s[c], 0.f);
                float v1 = fmaxf(acc[mt][nt][half * 2 + 1] + bias_s[c + 1], 0.f);
                h1[((size_t)(rs + r) * HP + gcol) >> 1] = hpack2(v0, v1);
            }
        }
    }
}

// ================= GEMM2: fp16 single-pass, tile 128x128, K=416, 3-stage =================
// stage: A@0 (128r, 10240B), B@10240 (128r, 10240B)
#define STAGE_SZ 20480
#define SMEM_SZ  (1024 + 3 * STAGE_SZ)

__global__ __launch_bounds__(256) void gemm2_mma(const float* __restrict__ b2,
                                                 float* __restrict__ out) {
    int bt = blockIdx.x;
    int rows = g_tile_rows[bt];
    if (rows == 0) return;
    int e  = g_tile_expert[bt];
    int rs = g_tile_rowstart[bt];
    int colbase = blockIdx.y * 128;

    extern __shared__ char smem[];
    uint32_t sb = smem_u32(smem);
    int tid = threadIdx.x;
    int wid = tid >> 5, lane = tid & 31;
    int wm = wid & 3, wn = wid >> 2;
    int tq = lane >> 2, tr = lane & 3;

    int* idx_s = reinterpret_cast<int*>(smem);
    float* bias_s = reinterpret_cast<float*>(smem + 512);
    if (tid < TILE_M) idx_s[tid] = g_idx_sorted[rs + tid];
    if (tid < 128) bias_s[tid] = b2[e * K2n + colbase + tid];
    __syncthreads();

    const uint4* w2 = g_w2t + (size_t)e * NW * (HP / 8);

    auto fill = [&](int stg, int kt) {
        uint32_t base = sb + 1024 + stg * STAGE_SZ;
#pragma unroll
        for (int i = tid; i < 512; i += 256) {
            int r = i >> 2, c4 = i & 3;
            uint32_t dA = base + r * 80 + c4 * 16;
            CP16(dA, g_h1 + (size_t)(rs + r) * (HP / 8) + kt * 4 + c4);
            uint32_t dB = base + 10240 + r * 80 + c4 * 16;
            CP16(dB, w2 + (size_t)(colbase + r) * (HP / 8) + kt * 4 + c4);
        }
    };

    float acc[2][8][4];
#pragma unroll
    for (int mt = 0; mt < 2; mt++)
#pragma unroll
        for (int nt = 0; nt < 8; nt++)
#pragma unroll
            for (int j = 0; j < 4; j++) acc[mt][nt][j] = 0.f;

    fill(0, 0); CP_COMMIT();
    fill(1, 1); CP_COMMIT();
    for (int it = 0; it < 13; it++) {
        if (it + 2 < 13) { fill((it + 2) % 3, it + 2); CP_COMMIT(); CP_WAIT2(); }
        else if (it + 1 < 13) CP_WAIT1();
        else CP_WAIT0();
        __syncthreads();
        const char* st = smem + 1024 + (it % 3) * STAGE_SZ;
#pragma unroll
        for (int ks = 0; ks < 2; ks++) {
            int kb = ks * 32 + tr * 4;
            uint32_t ah[2][4], bb[8][2];
#pragma unroll
            for (int mt = 0; mt < 2; mt++) {
                int r0 = wm * 32 + mt * 16 + tq;
                ah[mt][0] = *(const uint32_t*)(st + r0 * 80 + kb);
                ah[mt][1] = *(const uint32_t*)(st + (r0 + 8) * 80 + kb);
                ah[mt][2] = *(const uint32_t*)(st + r0 * 80 + kb + 16);
                ah[mt][3] = *(const uint32_t*)(st + (r0 + 8) * 80 + kb + 16);
            }
#pragma unroll
            for (int nt = 0; nt < 8; nt++) {
                int n = wn * 64 + nt * 8 + tq;
                bb[nt][0] = *(const uint32_t*)(st + 10240 + n * 80 + kb);
                bb[nt][1] = *(const uint32_t*)(st + 10240 + n * 80 + kb + 16);
            }
#pragma unroll
            for (int mt = 0; mt < 2; mt++)
#pragma unroll
                for (int nt = 0; nt < 8; nt++)
                    mma16816(acc[mt][nt], ah[mt], bb[nt]);
        }
        __syncthreads();
    }

#pragma unroll
    for (int mt = 0; mt < 2; mt++) {
        int r0 = wm * 32 + mt * 16 + tq;
#pragma unroll
        for (int nt = 0; nt < 8; nt++) {
            int c = wn * 64 + nt * 8 + tr * 2;
            int gcol = colbase + c;
#pragma unroll
            for (int half = 0; half < 2; half++) {
                int r = r0 + half * 8;
                if (r >= rows) continue;
                int b = idx_s[r];
                float2 v;
                v.x = acc[mt][nt][half * 2]     + bias_s[c];
                v.y = acc[mt][nt][half * 2 + 1] + bias_s[c + 1];
                float* dst = (gcol < Ln)
                    ? out + (size_t)b * Ln + gcol
                    : out + (size_t)Bn * Ln + (size_t)b * Ln + (gcol - Ln);
                *reinterpret_cast<float2*>(dst) = v;
            }
        }
    }
}

// ================= launch =================
extern "C" void kernel_launch(void* const* d_in, const int* in_sizes, int n_in,
                              void* d_out, int out_size) {
    const float* x  = (const float*)d_in[0];
    const void*  ai = d_in[1];
    const float* W1 = (const float*)d_in[2];
    const float* b1 = (const float*)d_in[3];
    const float* W2 = (const float*)d_in[4];
    const float* b2 = (const float*)d_in[5];
    float* out = (float*)d_out;

    cudaFuncSetAttribute(gemm1_mma, cudaFuncAttributeMaxDynamicSharedMemorySize, G1_SMEM);
    cudaFuncSetAttribute(gemm2_mma, cudaFuncAttributeMaxDynamicSharedMemorySize, SMEM_SZ);

    prep_kernel<<<PREP_GRID, 256>>>(ai, x, W1, W2);
    gemm1_mma<<<dim3(MAX_TILES, 5), 256, G1_SMEM>>>(b1);
    gemm2_mma<<<dim3(MAX_TILES, 4), 256, SMEM_SZ>>>(b2, out);
}

// round 12
// speedup vs baseline: 1.9845x; 1.1192x over previous
#include <cuda_runtime.h>
#include <cuda_fp16.h>
#include <cstdint>

// Problem constants
constexpr int Bn = 8192;   // batch
constexpr int Dn = 1024;   // input dim (K1)
constexpr int Hn = 400;    // hidden
constexpr int Ln = 256;    // half output
constexpr int En = 16;     // experts
constexpr int K2n = 512;   // 2L (N of GEMM2)
constexpr int HP = 416;    // hidden padded to 13*32 (K of GEMM2)
constexpr int NW = 512;    // padded N rows for transposed weights

#define TILE_M 128
#define MAX_TILES 80       // >= worst case sum ceil(ci/128) = 79
#define NT1 80             // GEMM1 N-tile (5 tiles * 80 = 400 exact)

// prep grid partition
#define PREP_SORT_BLOCKS   1
#define PREP_SPLIT_BLOCKS  (Bn * Dn / 4 / 256)          // 8192
#define PREP_TW1_BLOCKS    (32 * 13 * En)               // 6656
#define PREP_TW2_BLOCKS    (13 * 16 * En)               // 3328
#define PREP_GRID (PREP_SORT_BLOCKS + PREP_SPLIT_BLOCKS + PREP_TW1_BLOCKS + PREP_TW2_BLOCKS)

// ================= device scratch (zero-init, no allocs) =================
__device__ int   g_idx_sorted[Bn + TILE_M];
__device__ int   g_tile_expert[MAX_TILES];
__device__ int   g_tile_rowstart[MAX_TILES];
__device__ int   g_tile_rows[MAX_TILES];

// fp16 buffers, uint4 for 16B alignment
__device__ uint4 g_x[(size_t)Bn * Dn / 8];                 // [Bn][1024] fp16
__device__ uint4 g_w1t[(size_t)En * NW * Dn / 8];          // [E][512][1024] (n,k) fp16
__device__ uint4 g_w2t[(size_t)En * NW * HP / 8];          // [E][512][416] (n,k) fp16
__device__ uint4 g_h1[(size_t)(Bn + TILE_M) * HP / 8];     // [rows][416] fp16

// ================= helpers =================
__device__ __forceinline__ uint32_t smem_u32(const void* p) {
    uint32_t a;
    asm("{ .reg .u64 t; cvta.to.shared.u64 t, %1; cvt.u32.u64 %0, t; }" : "=r"(a) : "l"(p));
    return a;
}

#define CP16(dst_u32, src_ptr) \
    asm volatile("cp.async.cg.shared.global [%0], [%1], 16;" :: "r"(dst_u32), "l"(src_ptr))
#define CP_COMMIT() asm volatile("cp.async.commit_group;" ::: "memory")
#define CP_WAIT2()  asm volatile("cp.async.wait_group 2;" ::: "memory")
#define CP_WAIT1()  asm volatile("cp.async.wait_group 1;" ::: "memory")
#define CP_WAIT0()  asm volatile("cp.async.wait_group 0;" ::: "memory")

__device__ __forceinline__ void mma16816(float* d, const uint32_t* a, const uint32_t* b) {
    asm volatile(
        "mma.sync.aligned.m16n8k16.row.col.f32.f16.f16.f32 "
        "{%0,%1,%2,%3}, {%4,%5,%6,%7}, {%8,%9}, {%0,%1,%2,%3};"
        : "+f"(d[0]), "+f"(d[1]), "+f"(d[2]), "+f"(d[3])
        : "r"(a[0]), "r"(a[1]), "r"(a[2]), "r"(a[3]), "r"(b[0]), "r"(b[1]));
}

__device__ __forceinline__ uint32_t hpack2(float v0, float v1) {
    __half2 p;
    p.x = __float2half(v0);
    p.y = __float2half(v1);
    return *reinterpret_cast<uint32_t*>(&p);
}

// ================= fused prep kernel: sort | split_x | tw1 | tw2 =================
// launch_bounds(256, 8) forces <=32 regs -> high occupancy for the
// memory-bound branches (R11 ncu: 64 regs capped occ at 41%).
__global__ __launch_bounds__(256, 8) void prep_kernel(const void* __restrict__ ai,
                                                      const float* __restrict__ x,
                                                      const float* __restrict__ W1,
                                                      const float* __restrict__ W2) {
    int blk = blockIdx.x;
    int t = threadIdx.x;

    if (blk == 0) {
        // ---- sort: init + detect + count + prefix + tile list + scatter ----
        // No per-thread value cache: re-read ai in the scatter pass (L2-hot)
        // to keep register count low for the whole fused kernel.
        __shared__ int s_cnt[En], s_off[En], s_cur[En];
        __shared__ int s_is64;
        if (t < En) { s_cnt[t] = 0; s_cur[t] = 0; }
        if (t == 0) s_is64 = 1;
        if (t < TILE_M) g_idx_sorted[Bn + t] = 0;
        __syncthreads();

        const long long* a64 = (const long long*)ai;
        const int* a32 = (const int*)ai;
        for (int i = t; i < Bn / 2; i += 256) {
            long long v = a64[i];
            if (v < 0 || v >= En) s_is64 = 0;
        }
        __syncthreads();
        int is64 = s_is64;

        for (int i = t; i < Bn; i += 256) {
            int v = is64 ? (int)a64[i] : a32[i];
            atomicAdd(&s_cnt[v], 1);
        }
        __syncthreads();

        if (t == 0) {
            int off = 0, tb = 0;
            for (int e = 0; e < En; e++) {
                s_off[e] = off;
                int nt = (s_cnt[e] + TILE_M - 1) / TILE_M;
                for (int k = 0; k < nt; k++) {
                    g_tile_expert[tb + k]   = e;
                    g_tile_rowstart[tb + k] = off + k * TILE_M;
                    int rem = s_cnt[e] - k * TILE_M;
                    g_tile_rows[tb + k]     = rem < TILE_M ? rem : TILE_M;
                }
                tb += nt;
                off += s_cnt[e];
            }
            for (; tb < MAX_TILES; tb++) g_tile_rows[tb] = 0;
        }
        __syncthreads();

        for (int i = t; i < Bn; i += 256) {
            int e = is64 ? (int)a64[i] : a32[i];
            int pos = atomicAdd(&s_cur[e], 1);
            g_idx_sorted[s_off[e] + pos] = i;
        }
        return;
    }

    if (blk < PREP_SORT_BLOCKS + PREP_SPLIT_BLOCKS) {
        // ---- split_x: x -> fp16, + h1 pad zeroing ----
        int i = (blk - PREP_SORT_BLOCKS) * 256 + t;
        float4 v = reinterpret_cast<const float4*>(x)[i];
        uint2 p;
        p.x = hpack2(v.x, v.y);
        p.y = hpack2(v.z, v.w);
        reinterpret_cast<uint2*>(g_x)[i] = p;
        if (i < (Bn + TILE_M) * 8) {
            int row = i >> 3, c = i & 7;
            reinterpret_cast<uint32_t*>(g_h1)[(size_t)row * (HP / 2) + 200 + c] = 0;
        }
        return;
    }

    __shared__ float ts[32][33];
    int tx = t & 31, ty = t >> 5;    // 32 x 8

    if (blk < PREP_SORT_BLOCKS + PREP_SPLIT_BLOCKS + PREP_TW1_BLOCKS) {
        // ---- tw1: W1 [E][1024(k)][400(n)] -> fp16 [E][512(n)][1024(k)] ----
        int idx = blk - PREP_SORT_BLOCKS - PREP_SPLIT_BLOCKS;
        int k0 = (idx & 31) * 32;
        int n0 = ((idx >> 5) % 13) * 32;
        int e  = idx / (32 * 13);
        const float* W = W1 + (size_t)e * Dn * Hn;
#pragma unroll
        for (int i = 0; i < 32; i += 8) {
            int k = k0 + ty + i, n = n0 + tx;
            ts[ty + i][tx] = (n < Hn) ? W[(size_t)k * Hn + n] : 0.f;
        }
        __syncthreads();
        __half* wh = reinterpret_cast<__half*>(g_w1t);
#pragma unroll
        for (int i = 0; i < 32; i += 8) {
            int n = n0 + ty + i, k = k0 + tx;
            wh[((size_t)e * NW + n) * Dn + k] = __float2half(ts[tx][ty + i]);
        }
        return;
    }

    {
        // ---- tw2: W2 [E][400(k)][512(n)] -> fp16 [E][512(n)][416(k)] ----
        int idx = blk - PREP_SORT_BLOCKS - PREP_SPLIT_BLOCKS - PREP_TW1_BLOCKS;
        int k0 = (idx % 13) * 32;
        int n0 = ((idx / 13) & 15) * 32;
        int e  = idx / (13 * 16);
        const float* W = W2 + (size_t)e * Hn * K2n;
#pragma unroll
        for (int i = 0; i < 32; i += 8) {
            int k = k0 + ty + i, n = n0 + tx;
            ts[ty + i][tx] = (k < Hn) ? W[(size_t)k * K2n + n] : 0.f;
        }
        __syncthreads();
        __half* wh = reinterpret_cast<__half*>(g_w2t);
#pragma unroll
        for (int i = 0; i < 32; i += 8) {
            int n = n0 + ty + i, k = k0 + tx;
            wh[((size_t)e * NW + n) * HP + k] = __float2half(ts[tx][ty + i]);
        }
    }
}

// ================= GEMM1: fp16 single-pass, tile 128x80, 3-stage =================
// smem: [0,512) idx, [512,896) bias, [1024..) three stages
// stage (80B row stride): A r0-127 @0 (10240B), B @10240 (80 rows, 6400B)
#define G1_STAGE 16640
#define G1_SMEM  (1024 + 3 * G1_STAGE)

__global__ __launch_bounds__(256) void gemm1_mma(const float* __restrict__ b1) {
    int bt = blockIdx.x;
    int rows = g_tile_rows[bt];
    if (rows == 0) return;
    int e  = g_tile_expert[bt];
    int rs = g_tile_rowstart[bt];
    int colbase = blockIdx.y * NT1;

    extern __shared__ char smem[];
    uint32_t sb = smem_u32(smem);
    int tid = threadIdx.x;
    int wid = tid >> 5, lane = tid & 31;
    int wm = wid & 3, wn = wid >> 2;      // warps: 4 (M) x 2 (N); warp tile 32x40
    int tq = lane >> 2, tr = lane & 3;

    int* idx_s = reinterpret_cast<int*>(smem);
    float* bias_s = reinterpret_cast<float*>(smem + 512);
    if (tid < TILE_M) idx_s[tid] = g_idx_sorted[rs + tid];
    if (tid < NT1) bias_s[tid] = b1[e * Hn + colbase + tid];
    __syncthreads();

    const uint4* w1 = g_w1t + (size_t)e * NW * (Dn / 8);

    auto fill = [&](int stg, int kt) {
        uint32_t base = sb + 1024 + stg * G1_STAGE;
#pragma unroll
        for (int i = tid; i < 512; i += 256) {        // A: 128 rows x 4 uint4
            int r = i >> 2, c4 = i & 3;
            uint32_t d = base + r * 80 + c4 * 16;
            CP16(d, g_x + (size_t)idx_s[r] * 128 + kt * 4 + c4);
        }
#pragma unroll
        for (int i = tid; i < 320; i += 256) {        // B: 80 rows x 4 uint4
            int r = i >> 2, c4 = i & 3;
            uint32_t d = base + 10240 + r * 80 + c4 * 16;
            CP16(d, w1 + (size_t)(colbase + r) * 128 + kt * 4 + c4);
        }
    };

    float acc[2][5][4];
#pragma unroll
    for (int mt = 0; mt < 2; mt++)
#pragma unroll
        for (int nt = 0; nt < 5; nt++)
#pragma unroll
            for (int j = 0; j < 4; j++) acc[mt][nt][j] = 0.f;

    fill(0, 0); CP_COMMIT();
    fill(1, 1); CP_COMMIT();
    for (int it = 0; it < 32; it++) {
        if (it + 2 < 32) { fill((it + 2) % 3, it + 2); CP_COMMIT(); CP_WAIT2(); }
        else if (it + 1 < 32) CP_WAIT1();
        else CP_WAIT0();
        __syncthreads();
        const char* st = smem + 1024 + (it % 3) * G1_STAGE;
#pragma unroll
        for (int ks = 0; ks < 2; ks++) {
            int kb = ks * 32 + tr * 4;
            uint32_t ah[2][4], bb[5][2];
#pragma unroll
            for (int mt = 0; mt < 2; mt++) {
                int r0 = wm * 32 + mt * 16 + tq;
                ah[mt][0] = *(const uint32_t*)(st + r0 * 80 + kb);
                ah[mt][1] = *(const uint32_t*)(st + (r0 + 8) * 80 + kb);
                ah[mt][2] = *(const uint32_t*)(st + r0 * 80 + kb + 16);
                ah[mt][3] = *(const uint32_t*)(st + (r0 + 8) * 80 + kb + 16);
            }
#pragma unroll
            for (int nt = 0; nt < 5; nt++) {
                int n = wn * 40 + nt * 8 + tq;
                bb[nt][0] = *(const uint32_t*)(st + 10240 + n * 80 + kb);
                bb[nt][1] = *(const uint32_t*)(st + 10240 + n * 80 + kb + 16);
            }
#pragma unroll
            for (int mt = 0; mt < 2; mt++)
#pragma unroll
                for (int nt = 0; nt < 5; nt++)
                    mma16816(acc[mt][nt], ah[mt], bb[nt]);
        }
        __syncthreads();
    }

    // epilogue: bias + relu -> fp16 h1
    uint32_t* h1 = reinterpret_cast<uint32_t*>(g_h1);
#pragma unroll
    for (int mt = 0; mt < 2; mt++) {
        int r0 = wm * 32 + mt * 16 + tq;
#pragma unroll
        for (int nt = 0; nt < 5; nt++) {
            int c = wn * 40 + nt * 8 + tr * 2;
            int gcol = colbase + c;
#pragma unroll
            for (int half = 0; half < 2; half++) {
                int r = r0 + half * 8;
                if (r >= rows) continue;
                float v0 = fmaxf(acc[mt][nt][half * 2]     + bias_s[c], 0.f);
                float v1 = fmaxf(acc[mt][nt][half * 2 + 1] + bias_s[c + 1], 0.f);
                h1[((size_t)(rs + r) * HP + gcol) >> 1] = hpack2(v0, v1);
            }
        }
    }
}

// ================= GEMM2: fp16 single-pass, tile 128x128, K=416, 3-stage =================
// stage: A@0 (128r, 10240B), B@10240 (128r, 10240B)
#define STAGE_SZ 20480
#define SMEM_SZ  (1024 + 3 * STAGE_SZ)

__global__ __launch_bounds__(256) void gemm2_mma(const float* __restrict__ b2,
                                                 float* __restrict__ out) {
    int bt = blockIdx.x;
    int rows = g_tile_rows[bt];
    if (rows == 0) return;
    int e  = g_tile_expert[bt];
    int rs = g_tile_rowstart[bt];
    int colbase = blockIdx.y * 128;

    extern __shared__ char smem[];
    uint32_t sb = smem_u32(smem);
    int tid = threadIdx.x;
    int wid = tid >> 5, lane = tid & 31;
    int wm = wid & 3, wn = wid >> 2;
    int tq = lane >> 2, tr = lane & 3;

    int* idx_s = reinterpret_cast<int*>(smem);
    float* bias_s = reinterpret_cast<float*>(smem + 512);
    if (tid < TILE_M) idx_s[tid] = g_idx_sorted[rs + tid];
    if (tid < 128) bias_s[tid] = b2[e * K2n + colbase + tid];
    __syncthreads();

    const uint4* w2 = g_w2t + (size_t)e * NW * (HP / 8);

    auto fill = [&](int stg, int kt) {
        uint32_t base = sb + 1024 + stg * STAGE_SZ;
#pragma unroll
        for (int i = tid; i < 512; i += 256) {
            int r = i >> 2, c4 = i & 3;
            uint32_t dA = base + r * 80 + c4 * 16;
            CP16(dA, g_h1 + (size_t)(rs + r) * (HP / 8) + kt * 4 + c4);
            uint32_t dB = base + 10240 + r * 80 + c4 * 16;
            CP16(dB, w2 + (size_t)(colbase + r) * (HP / 8) + kt * 4 + c4);
        }
    };

    float acc[2][8][4];
#pragma unroll
    for (int mt = 0; mt < 2; mt++)
#pragma unroll
        for (int nt = 0; nt < 8; nt++)
#pragma unroll
            for (int j = 0; j < 4; j++) acc[mt][nt][j] = 0.f;

    fill(0, 0); CP_COMMIT();
    fill(1, 1); CP_COMMIT();
    for (int it = 0; it < 13; it++) {
        if (it + 2 < 13) { fill((it + 2) % 3, it + 2); CP_COMMIT(); CP_WAIT2(); }
        else if (it + 1 < 13) CP_WAIT1();
        else CP_WAIT0();
        __syncthreads();
        const char* st = smem + 1024 + (it % 3) * STAGE_SZ;
#pragma unroll
        for (int ks = 0; ks < 2; ks++) {
            int kb = ks * 32 + tr * 4;
            uint32_t ah[2][4], bb[8][2];
#pragma unroll
            for (int mt = 0; mt < 2; mt++) {
                int r0 = wm * 32 + mt * 16 + tq;
                ah[mt][0] = *(const uint32_t*)(st + r0 * 80 + kb);
                ah[mt][1] = *(const uint32_t*)(st + (r0 + 8) * 80 + kb);
                ah[mt][2] = *(const uint32_t*)(st + r0 * 80 + kb + 16);
                ah[mt][3] = *(const uint32_t*)(st + (r0 + 8) * 80 + kb + 16);
            }
#pragma unroll
            for (int nt = 0; nt < 8; nt++) {
                int n = wn * 64 + nt * 8 + tq;
                bb[nt][0] = *(const uint32_t*)(st + 10240 + n * 80 + kb);
                bb[nt][1] = *(const uint32_t*)(st + 10240 + n * 80 + kb + 16);
            }
#pragma unroll
            for (int mt = 0; mt < 2; mt++)
#pragma unroll
                for (int nt = 0; nt < 8; nt++)
                    mma16816(acc[mt][nt], ah[mt], bb[nt]);
        }
        __syncthreads();
    }

#pragma unroll
    for (int mt = 0; mt < 2; mt++) {
        int r0 = wm * 32 + mt * 16 + tq;
#pragma unroll
        for (int nt = 0; nt < 8; nt++) {
            int c = wn * 64 + nt * 8 + tr * 2;
            int gcol = colbase + c;
#pragma unroll
            for (int half = 0; half < 2; half++) {
                int r = r0 + half * 8;
                if (r >= rows) continue;
                int b = idx_s[r];
                float2 v;
                v.x = acc[mt][nt][half * 2]     + bias_s[c];
                v.y = acc[mt][nt][half * 2 + 1] + bias_s[c + 1];
                float* dst = (gcol < Ln)
                    ? out + (size_t)b * Ln + gcol
                    : out + (size_t)Bn * Ln + (size_t)b * Ln + (gcol - Ln);
                *reinterpret_cast<float2*>(dst) = v;
            }
        }
    }
}

// ================= launch =================
extern "C" void kernel_launch(void* const* d_in, const int* in_sizes, int n_in,
                              void* d_out, int out_size) {
    const float* x  = (const float*)d_in[0];
    const void*  ai = d_in[1];
    const float* W1 = (const float*)d_in[2];
    const float* b1 = (const float*)d_in[3];
    const float* W2 = (const float*)d_in[4];
    const float* b2 = (const float*)d_in[5];
    float* out = (float*)d_out;

    cudaFuncSetAttribute(gemm1_mma, cudaFuncAttributeMaxDynamicSharedMemorySize, G1_SMEM);
    cudaFuncSetAttribute(gemm2_mma, cudaFuncAttributeMaxDynamicSharedMemorySize, SMEM_SZ);

    prep_kernel<<<PREP_GRID, 256>>>(ai, x, W1, W2);
    gemm1_mma<<<dim3(MAX_TILES, 5), 256, G1_SMEM>>>(b1);
    gemm2_mma<<<dim3(MAX_TILES, 4), 256, SMEM_SZ>>>(b2, out);
}

// round 14
// speedup vs baseline: 2.1546x; 1.0857x over previous
#include <cuda_runtime.h>
#include <cuda_fp16.h>
#include <cstdint>

// Problem constants
constexpr int Bn = 8192;   // batch
constexpr int Dn = 1024;   // input dim (K1)
constexpr int Hn = 400;    // hidden
constexpr int Ln = 256;    // half output
constexpr int En = 16;     // experts
constexpr int K2n = 512;   // 2L (N of GEMM2)
constexpr int HP = 416;    // hidden padded to 13*32 (K of GEMM2)
constexpr int NW = 512;    // padded N rows for transposed weights

#define TILE_M 128
#define MAX_TILES 80       // >= worst case sum ceil(ci/128) = 79
#define NT1 80             // GEMM1 N-tile (5 tiles * 80 = 400 exact)

// prep grid partition (tw2 moved into gemm1's grid)
#define PREP_SORT_BLOCKS   1
#define PREP_SPLIT_BLOCKS  (Bn * Dn / 4 / 256)          // 8192
#define PREP_TW1_BLOCKS    (32 * 13 * En)               // 6656
#define PREP_GRID (PREP_SORT_BLOCKS + PREP_SPLIT_BLOCKS + PREP_TW1_BLOCKS)

#define TW2_BLOCKS (13 * 16 * En)                       // 3328
#define G1_MMA_BLOCKS (MAX_TILES * 5)                   // 400
#define G1_GRID (G1_MMA_BLOCKS + TW2_BLOCKS)

// ================= device scratch (zero-init, no allocs) =================
__device__ int   g_idx_sorted[Bn + TILE_M];
__device__ int   g_tile_expert[MAX_TILES];
__device__ int   g_tile_rowstart[MAX_TILES];
__device__ int   g_tile_rows[MAX_TILES];

// fp16 buffers, uint4 for 16B alignment
__device__ uint4 g_x[(size_t)Bn * Dn / 8];                 // [Bn][1024] fp16
__device__ uint4 g_w1t[(size_t)En * NW * Dn / 8];          // [E][512][1024] (n,k) fp16
__device__ uint4 g_w2t[(size_t)En * NW * HP / 8];          // [E][512][416] (n,k) fp16
__device__ uint4 g_h1[(size_t)(Bn + TILE_M) * HP / 8];     // [rows][416] fp16

// ================= helpers =================
__device__ __forceinline__ uint32_t smem_u32(const void* p) {
    uint32_t a;
    asm("{ .reg .u64 t; cvta.to.shared.u64 t, %1; cvt.u32.u64 %0, t; }" : "=r"(a) : "l"(p));
    return a;
}

#define CP16(dst_u32, src_ptr) \
    asm volatile("cp.async.cg.shared.global [%0], [%1], 16;" :: "r"(dst_u32), "l"(src_ptr))
#define CP_COMMIT() asm volatile("cp.async.commit_group;" ::: "memory")
#define CP_WAIT2()  asm volatile("cp.async.wait_group 2;" ::: "memory")
#define CP_WAIT1()  asm volatile("cp.async.wait_group 1;" ::: "memory")
#define CP_WAIT0()  asm volatile("cp.async.wait_group 0;" ::: "memory")

__device__ __forceinline__ void mma16816(float* d, const uint32_t* a, const uint32_t* b) {
    asm volatile(
        "mma.sync.aligned.m16n8k16.row.col.f32.f16.f16.f32 "
        "{%0,%1,%2,%3}, {%4,%5,%6,%7}, {%8,%9}, {%0,%1,%2,%3};"
        : "+f"(d[0]), "+f"(d[1]), "+f"(d[2]), "+f"(d[3])
        : "r"(a[0]), "r"(a[1]), "r"(a[2]), "r"(a[3]), "r"(b[0]), "r"(b[1]));
}

__device__ __forceinline__ uint32_t hpack2(float v0, float v1) {
    __half2 p;
    p.x = __float2half(v0);
    p.y = __float2half(v1);
    return *reinterpret_cast<uint32_t*>(&p);
}

// ================= fused prep kernel: sort | split_x | tw1 =================
__global__ __launch_bounds__(256, 8) void prep_kernel(const void* __restrict__ ai,
                                                      const float* __restrict__ x,
                                                      const float* __restrict__ W1) {
    int blk = blockIdx.x;
    int t = threadIdx.x;

    if (blk == 0) {
        // ---- sort ----
        __shared__ int s_cnt[En], s_off[En], s_cur[En];
        __shared__ int s_is64;
        if (t < En) { s_cnt[t] = 0; s_cur[t] = 0; }
        if (t == 0) s_is64 = 1;
        if (t < TILE_M) g_idx_sorted[Bn + t] = 0;
        __syncthreads();

        const long long* a64 = (const long long*)ai;
        const int* a32 = (const int*)ai;
        for (int i = t; i < Bn / 2; i += 256) {
            long long v = a64[i];
            if (v < 0 || v >= En) s_is64 = 0;
        }
        __syncthreads();
        int is64 = s_is64;

        for (int i = t; i < Bn; i += 256) {
            int v = is64 ? (int)a64[i] : a32[i];
            atomicAdd(&s_cnt[v], 1);
        }
        __syncthreads();

        if (t == 0) {
            int off = 0, tb = 0;
            for (int e = 0; e < En; e++) {
                s_off[e] = off;
                int nt = (s_cnt[e] + TILE_M - 1) / TILE_M;
                for (int k = 0; k < nt; k++) {
                    g_tile_expert[tb + k]   = e;
                    g_tile_rowstart[tb + k] = off + k * TILE_M;
                    int rem = s_cnt[e] - k * TILE_M;
                    g_tile_rows[tb + k]     = rem < TILE_M ? rem : TILE_M;
                }
                tb += nt;
                off += s_cnt[e];
            }
            for (; tb < MAX_TILES; tb++) g_tile_rows[tb] = 0;
        }
        __syncthreads();

        for (int i = t; i < Bn; i += 256) {
            int e = is64 ? (int)a64[i] : a32[i];
            int pos = atomicAdd(&s_cur[e], 1);
            g_idx_sorted[s_off[e] + pos] = i;
        }
        return;
    }

    if (blk < PREP_SORT_BLOCKS + PREP_SPLIT_BLOCKS) {
        // ---- split_x + h1 pad zeroing ----
        int i = (blk - PREP_SORT_BLOCKS) * 256 + t;
        float4 v = reinterpret_cast<const float4*>(x)[i];
        uint2 p;
        p.x = hpack2(v.x, v.y);
        p.y = hpack2(v.z, v.w);
        reinterpret_cast<uint2*>(g_x)[i] = p;
        if (i < (Bn + TILE_M) * 8) {
            int row = i >> 3, c = i & 7;
            reinterpret_cast<uint32_t*>(g_h1)[(size_t)row * (HP / 2) + 200 + c] = 0;
        }
        return;
    }

    {
        // ---- tw1: W1 [E][1024(k)][400(n)] -> fp16 [E][512(n)][1024(k)] ----
        __shared__ float ts[32][33];
        int tx = t & 31, ty = t >> 5;
        int idx = blk - PREP_SORT_BLOCKS - PREP_SPLIT_BLOCKS;
        int k0 = (idx & 31) * 32;
        int n0 = ((idx >> 5) % 13) * 32;
        int e  = idx / (32 * 13);
        const float* W = W1 + (size_t)e * Dn * Hn;
#pragma unroll
        for (int i = 0; i < 32; i += 8) {
            int k = k0 + ty + i, n = n0 + tx;
            ts[ty + i][tx] = (n < Hn) ? W[(size_t)k * Hn + n] : 0.f;
        }
        __syncthreads();
        __half* wh = reinterpret_cast<__half*>(g_w1t);
#pragma unroll
        for (int i = 0; i < 32; i += 8) {
            int n = n0 + ty + i, k = k0 + tx;
            wh[((size_t)e * NW + n) * Dn + k] = __float2half(ts[tx][ty + i]);
        }
    }
}

// ================= GEMM1: fp16 single-pass, tile 128x80, BK=64, 2-stage =================
// plus tw2 conversion blocks appended to the grid (overlap with MMA work).
// smem: [0,512) idx, [512,896) bias, [1024..) two stages
// stage (144B row stride, 128B data): A r0-127 @0 (18432B), B @18432 (80 rows, 11520B)
#define G1_STAGE 29952
#define G1_SMEM  (1024 + 2 * G1_STAGE)

__global__ __launch_bounds__(256) void gemm1_mma(const float* __restrict__ b1,
                                                 const float* __restrict__ W2) {
    int gx = blockIdx.x;
    int tid = threadIdx.x;
    extern __shared__ char smem[];

    if (gx >= G1_MMA_BLOCKS) {
        // ---- tw2: W2 [E][400(k)][512(n)] -> fp16 [E][512(n)][416(k)] ----
        // Runs concurrently with the MMA blocks (memory pipe vs tensor pipe).
        float* ts = reinterpret_cast<float*>(smem);   // 32x33 floats
        int tx = tid & 31, ty = tid >> 5;
        int idx = gx - G1_MMA_BLOCKS;
        int k0 = (idx % 13) * 32;
        int n0 = ((idx / 13) & 15) * 32;
        int e  = idx / (13 * 16);
        const float* W = W2 + (size_t)e * Hn * K2n;
#pragma unroll
        for (int i = 0; i < 32; i += 8) {
            int k = k0 + ty + i, n = n0 + tx;
            ts[(ty + i) * 33 + tx] = (k < Hn) ? W[(size_t)k * K2n + n] : 0.f;
        }
        __syncthreads();
        __half* wh = reinterpret_cast<__half*>(g_w2t);
#pragma unroll
        for (int i = 0; i < 32; i += 8) {
            int n = n0 + ty + i, k = k0 + tx;
            wh[((size_t)e * NW + n) * HP + k] = __float2half(ts[tx * 33 + ty + i]);
        }
        return;
    }

    int bt = gx / 5;
    int rows = g_tile_rows[bt];
    if (rows == 0) return;
    int e  = g_tile_expert[bt];
    int rs = g_tile_rowstart[bt];
    int colbase = (gx % 5) * NT1;

    uint32_t sb = smem_u32(smem);
    int wid = tid >> 5, lane = tid & 31;
    int wm = wid & 3, wn = wid >> 2;      // warps: 4 (M) x 2 (N); warp tile 32x40
    int tq = lane >> 2, tr = lane & 3;

    int* idx_s = reinterpret_cast<int*>(smem);
    float* bias_s = reinterpret_cast<float*>(smem + 512);
    if (tid < TILE_M) idx_s[tid] = g_idx_sorted[rs + tid];
    if (tid < NT1) bias_s[tid] = b1[e * Hn + colbase + tid];
    __syncthreads();

    const uint4* w1 = g_w1t + (size_t)e * NW * (Dn / 8);

    auto fill = [&](int stg, int kt) {
        uint32_t base = sb + 1024 + stg * G1_STAGE;
#pragma unroll
        for (int i = tid; i < 1024; i += 256) {       // A: 128 rows x 8 uint4
            int r = i >> 3, c8 = i & 7;
            uint32_t d = base + r * 144 + c8 * 16;
            CP16(d, g_x + (size_t)idx_s[r] * 128 + kt * 8 + c8);
        }
#pragma unroll
        for (int i = tid; i < 640; i += 256) {        // B: 80 rows x 8 uint4
            int r = i >> 3, c8 = i & 7;
            uint32_t d = base + 18432 + r * 144 + c8 * 16;
            CP16(d, w1 + (size_t)(colbase + r) * 128 + kt * 8 + c8);
        }
    };

    float acc[2][5][4];
#pragma unroll
    for (int mt = 0; mt < 2; mt++)
#pragma unroll
        for (int nt = 0; nt < 5; nt++)
#pragma unroll
            for (int j = 0; j < 4; j++) acc[mt][nt][j] = 0.f;

    fill(0, 0); CP_COMMIT();
    for (int it = 0; it < 16; it++) {                 // BK=64, 16 iterations
        if (it + 1 < 16) { fill((it + 1) & 1, it + 1); CP_COMMIT(); CP_WAIT1(); }
        else CP_WAIT0();
        __syncthreads();
        const char* st = smem + 1024 + (it & 1) * G1_STAGE;
#pragma unroll
        for (int ks = 0; ks < 4; ks++) {              // 4 k16 sub-chunks
            int kb = ks * 32 + tr * 4;
            uint32_t ah[2][4], bb[5][2];
#pragma unroll
            for (int mt = 0; mt < 2; mt++) {
                int r0 = wm * 32 + mt * 16 + tq;
                ah[mt][0] = *(const uint32_t*)(st + r0 * 144 + kb);
                ah[mt][1] = *(const uint32_t*)(st + (r0 + 8) * 144 + kb);
                ah[mt][2] = *(const uint32_t*)(st + r0 * 144 + kb + 16);
                ah[mt][3] = *(const uint32_t*)(st + (r0 + 8) * 144 + kb + 16);
            }
#pragma unroll
            for (int nt = 0; nt < 5; nt++) {
                int n = wn * 40 + nt * 8 + tq;
                bb[nt][0] = *(const uint32_t*)(st + 18432 + n * 144 + kb);
                bb[nt][1] = *(const uint32_t*)(st + 18432 + n * 144 + kb + 16);
            }
#pragma unroll
            for (int mt = 0; mt < 2; mt++)
#pragma unroll
                for (int nt = 0; nt < 5; nt++)
                    mma16816(acc[mt][nt], ah[mt], bb[nt]);
        }
        __syncthreads();
    }

    // epilogue: bias + relu -> fp16 h1
    uint32_t* h1 = reinterpret_cast<uint32_t*>(g_h1);
#pragma unroll
    for (int mt = 0; mt < 2; mt++) {
        int r0 = wm * 32 + mt * 16 + tq;
#pragma unroll
        for (int nt = 0; nt < 5; nt++) {
            int c = wn * 40 + nt * 8 + tr * 2;
            int gcol = colbase + c;
#pragma unroll
            for (int half = 0; half < 2; half++) {
                int r = r0 + half * 8;
                if (r >= rows) continue;
                float v0 = fmaxf(acc[mt][nt][half * 2]     + bias_s[c], 0.f);
                float v1 = fmaxf(acc[mt][nt][half * 2 + 1] + bias_s[c + 1], 0.f);
                h1[((size_t)(rs + r) * HP + gcol) >> 1] = hpack2(v0, v1);
            }
        }
    }
}

// ================= GEMM2: fp16 single-pass, tile 128x128, K=416, 3-stage =================
// stage: A@0 (128r, 10240B), B@10240 (128r, 10240B)
#define STAGE_SZ 20480
#define SMEM_SZ  (1024 + 3 * STAGE_SZ)

__global__ __launch_bounds__(256) void gemm2_mma(const float* __restrict__ b2,
                                                 float* __restrict__ out) {
    int bt = blockIdx.x;
    int rows = g_tile_rows[bt];
    if (rows == 0) return;
    int e  = g_tile_expert[bt];
    int rs = g_tile_rowstart[bt];
    int colbase = blockIdx.y * 128;

    extern __shared__ char smem[];
    uint32_t sb = smem_u32(smem);
    int tid = threadIdx.x;
    int wid = tid >> 5, lane = tid & 31;
    int wm = wid & 3, wn = wid >> 2;
    int tq = lane >> 2, tr = lane & 3;

    int* idx_s = reinterpret_cast<int*>(smem);
    float* bias_s = reinterpret_cast<float*>(smem + 512);
    if (tid < TILE_M) idx_s[tid] = g_idx_sorted[rs + tid];
    if (tid < 128) bias_s[tid] = b2[e * K2n + colbase + tid];
    __syncthreads();

    const uint4* w2 = g_w2t + (size_t)e * NW * (HP / 8);

    auto fill = [&](int stg, int kt) {
        uint32_t base = sb + 1024 + stg * STAGE_SZ;
#pragma unroll
        for (int i = tid; i < 512; i += 256) {
            int r = i >> 2, c4 = i & 3;
            uint32_t dA = base + r * 80 + c4 * 16;
            CP16(dA, g_h1 + (size_t)(rs + r) * (HP / 8) + kt * 4 + c4);
            uint32_t dB = base + 10240 + r * 80 + c4 * 16;
            CP16(dB, w2 + (size_t)(colbase + r) * (HP / 8) + kt * 4 + c4);
        }
    };

    float acc[2][8][4];
#pragma unroll
    for (int mt = 0; mt < 2; mt++)
#pragma unroll
        for (int nt = 0; nt < 8; nt++)
#pragma unroll
            for (int j = 0; j < 4; j++) acc[mt][nt][j] = 0.f;

    fill(0, 0); CP_COMMIT();
    fill(1, 1); CP_COMMIT();
    for (int it = 0; it < 13; it++) {
        if (it + 2 < 13) { fill((it + 2) % 3, it + 2); CP_COMMIT(); CP_WAIT2(); }
        else if (it + 1 < 13) CP_WAIT1();
        else CP_WAIT0();
        __syncthreads();
        const char* st = smem + 1024 + (it % 3) * STAGE_SZ;
#pragma unroll
        for (int ks = 0; ks < 2; ks++) {
            int kb = ks * 32 + tr * 4;
            uint32_t ah[2][4], bb[8][2];
#pragma unroll
            for (int mt = 0; mt < 2; mt++) {
                int r0 = wm * 32 + mt * 16 + tq;
                ah[mt][0] = *(const uint32_t*)(st + r0 * 80 + kb);
                ah[mt][1] = *(const uint32_t*)(st + (r0 + 8) * 80 + kb);
                ah[mt][2] = *(const uint32_t*)(st + r0 * 80 + kb + 16);
                ah[mt][3] = *(const uint32_t*)(st + (r0 + 8) * 80 + kb + 16);
            }
#pragma unroll
            for (int nt = 0; nt < 8; nt++) {
                int n = wn * 64 + nt * 8 + tq;
                bb[nt][0] = *(const uint32_t*)(st + 10240 + n * 80 + kb);
                bb[nt][1] = *(const uint32_t*)(st + 10240 + n * 80 + kb + 16);
            }
#pragma unroll
            for (int mt = 0; mt < 2; mt++)
#pragma unroll
                for (int nt = 0; nt < 8; nt++)
                    mma16816(acc[mt][nt], ah[mt], bb[nt]);
        }
        __syncthreads();
    }

#pragma unroll
    for (int mt = 0; mt < 2; mt++) {
        int r0 = wm * 32 + mt * 16 + tq;
#pragma unroll
        for (int nt = 0; nt < 8; nt++) {
            int c = wn * 64 + nt * 8 + tr * 2;
            int gcol = colbase + c;
#pragma unroll
            for (int half = 0; half < 2; half++) {
                int r = r0 + half * 8;
                if (r >= rows) continue;
                int b = idx_s[r];
                float2 v;
                v.x = acc[mt][nt][half * 2]     + bias_s[c];
                v.y = acc[mt][nt][half * 2 + 1] + bias_s[c + 1];
                float* dst = (gcol < Ln)
                    ? out + (size_t)b * Ln + gcol
                    : out + (size_t)Bn * Ln + (size_t)b * Ln + (gcol - Ln);
                *reinterpret_cast<float2*>(dst) = v;
            }
        }
    }
}

// ================= launch =================
extern "C" void kernel_launch(void* const* d_in, const int* in_sizes, int n_in,
                              void* d_out, int out_size) {
    const float* x  = (const float*)d_in[0];
    const void*  ai = d_in[1];
    const float* W1 = (const float*)d_in[2];
    const float* b1 = (const float*)d_in[3];
    const float* W2 = (const float*)d_in[4];
    const float* b2 = (const float*)d_in[5];
    float* out = (float*)d_out;

    cudaFuncSetAttribute(gemm1_mma, cudaFuncAttributeMaxDynamicSharedMemorySize, G1_SMEM);
    cudaFuncSetAttribute(gemm2_mma, cudaFuncAttributeMaxDynamicSharedMemorySize, SMEM_SZ);

    prep_kernel<<<PREP_GRID, 256>>>(ai, x, W1);
    gemm1_mma<<<G1_GRID, 256, G1_SMEM>>>(b1, W2);
    gemm2_mma<<<dim3(MAX_TILES, 4), 256, SMEM_SZ>>>(b2, out);
}